// round 13
// baseline (speedup 1.0000x reference)
#include <cuda_runtime.h>
#include <cuda_fp16.h>
#include <math.h>
#include <stdint.h>

#define BB   2
#define SS   2048
#define DD   2048
#define HH   16
#define HD   128
#define FF   8192
#define MM   (BB*SS)          // 4096
#define QKVW (3*DD)           // 6144

// ---------------- scratch ----------------
__device__ __half g_qkvh[(size_t)MM*QKVW];     // fp16 row-major qkv
// fp16 packed (tiled [rows/128][K/64][128][64], SW128)
__device__ __half g_xn2 [(size_t)MM*DD];
__device__ __half g_att2[(size_t)MM*DD];
__device__ __half g_h2  [(size_t)MM*DD];
__device__ __half g_gg2 [(size_t)MM*FF];
__device__ __half g_wqkv2[(size_t)QKVW*DD];
__device__ __half g_wout2[(size_t)DD*DD];
__device__ __half g_w132[(size_t)2*FF*DD];     // w1/w3 row-interleaved
__device__ __half g_w22 [(size_t)DD*FF];

// ---------------- PTX helpers -------------------------------------------------
__device__ __forceinline__ uint32_t smem_u32(const void* p) {
    uint32_t a;
    asm("{ .reg .u64 t; cvta.to.shared.u64 t, %1; cvt.u32.u64 %0, t; }" : "=r"(a) : "l"(p));
    return a;
}
__device__ __forceinline__ uint32_t elect_one() {
    uint32_t p;
    asm volatile("{ .reg .pred p; elect.sync _|p, 0xFFFFFFFF; selp.b32 %0,1,0,p; }" : "=r"(p));
    return p;
}
#define MBAR_INIT(a, c) \
    asm volatile("mbarrier.init.shared.b64 [%0], %1;" :: "r"(a), "r"(c) : "memory")
#define MBAR_EXPECT(a, b) \
    asm volatile("mbarrier.arrive.expect_tx.shared.b64 _, [%0], %1;" :: "r"(a), "r"(b) : "memory")
#define MBAR_ARRIVE(a) \
    asm volatile("mbarrier.arrive.shared.b64 _, [%0];" :: "r"(a) : "memory")
#define MBAR_WAIT(a, ph) do { uint32_t _m=(a), _p=(ph), _d;                                   \
    asm volatile("{ .reg .pred p; mbarrier.try_wait.parity.acquire.cta.shared::cta.b64 p, [%1], %2; selp.b32 %0,1,0,p; }" \
                 : "=r"(_d) : "r"(_m), "r"(_p) : "memory");                                   \
    if (!_d) {                                                                                \
      asm volatile("{ .reg .pred P1; WL%=: mbarrier.try_wait.parity.acquire.cta.shared::cta.b64 P1, [%0], %1, 0x989680; @P1 bra.uni WD%=; bra.uni WL%=; WD%=: }" \
                   :: "r"(_m), "r"(_p) : "memory"); } } while(0)
#define BULK_G2S(d, s, n, m) \
    asm volatile("cp.async.bulk.shared::cta.global.mbarrier::complete_tx::bytes [%0], [%1], %2, [%3];" \
                 :: "r"(d), "l"(s), "r"(n), "r"(m) : "memory")
#define LDSM_X4(r0, r1, r2, r3, a) \
    asm volatile("ldmatrix.sync.aligned.m8n8.x4.shared.b16 {%0,%1,%2,%3}, [%4];" \
                 : "=r"(r0), "=r"(r1), "=r"(r2), "=r"(r3) : "r"(a))
#define LDSM_X4T(r0, r1, r2, r3, a) \
    asm volatile("ldmatrix.sync.aligned.m8n8.x4.trans.shared.b16 {%0,%1,%2,%3}, [%4];" \
                 : "=r"(r0), "=r"(r1), "=r"(r2), "=r"(r3) : "r"(a))
#define MMA16816H(d, av, bv) \
    asm volatile("mma.sync.aligned.m16n8k16.row.col.f32.f16.f16.f32 " \
                 "{%0,%1,%2,%3}, {%4,%5,%6,%7}, {%8,%9}, {%0,%1,%2,%3};" \
                 : "+f"((d)[0]), "+f"((d)[1]), "+f"((d)[2]), "+f"((d)[3]) \
                 : "r"((av)[0]), "r"((av)[1]), "r"((av)[2]), "r"((av)[3]), \
                   "r"((bv)[0]), "r"((bv)[1]))

// ---------------- fp16 pack helpers --------------------------------------------
__device__ __forceinline__ uint32_t h2pack(float v0, float v1) {
    return (uint32_t)__half_as_ushort(__float2half_rn(v0))
         | ((uint32_t)__half_as_ushort(__float2half_rn(v1)) << 16);
}
__device__ __forceinline__ void pack4H(char* base, int ktK, int m, int n, float4 v) {
    const int mt = m >> 7, mr = m & 127;
    const int kt = n >> 6, c = n & 63;
    const size_t tb = ((size_t)mt * ktK + kt) * 16384;
    uint32_t off = (uint32_t)(mr * 128 + c * 2);
    off ^= (off >> 3) & 0x70;
    *(uint2*)(base + tb + off) = make_uint2(h2pack(v.x, v.y), h2pack(v.z, v.w));
}
__device__ __forceinline__ void pack2H(char* base, int ktK, int m, int n, float v0, float v1) {
    const int mt = m >> 7, mr = m & 127;
    const int kt = n >> 6, c = n & 63;
    const size_t tb = ((size_t)mt * ktK + kt) * 16384;
    uint32_t off = (uint32_t)(mr * 128 + c * 2);
    off ^= (off >> 3) & 0x70;
    *(uint32_t*)(base + tb + off) = h2pack(v0, v1);
}

// ---------------- RMSNorm -> packed fp16 ---------------------------------------
__global__ __launch_bounds__(256) void rmsnorm_pack(
    const float* __restrict__ x, const float* __restrict__ w, __half* __restrict__ dst)
{
    const int row = blockIdx.x;
    const float4* xr = (const float4*)(x + (size_t)row * DD);
    float4 a = xr[threadIdx.x];
    float4 b = xr[threadIdx.x + 256];
    float ss = a.x*a.x + a.y*a.y + a.z*a.z + a.w*a.w
             + b.x*b.x + b.y*b.y + b.z*b.z + b.w*b.w;
    #pragma unroll
    for (int o = 16; o; o >>= 1) ss += __shfl_xor_sync(0xffffffffu, ss, o);
    __shared__ float sred[8];
    if ((threadIdx.x & 31) == 0) sred[threadIdx.x >> 5] = ss;
    __syncthreads();
    float tot = sred[0]+sred[1]+sred[2]+sred[3]+sred[4]+sred[5]+sred[6]+sred[7];
    float sc = rsqrtf(tot * (1.0f / DD) + 1e-5f);

    const float4* wr = (const float4*)w;
    #pragma unroll
    for (int g = 0; g < 2; g++) {
        const int gi = threadIdx.x + g*256;
        float4 v = (g == 0) ? a : b;
        float4 wv = wr[gi];
        v.x *= sc * wv.x; v.y *= sc * wv.y; v.z *= sc * wv.z; v.w *= sc * wv.w;
        pack4H((char*)dst, DD/64, row, gi*4, v);
    }
}

// ---------------- all weight conversions in ONE launch --------------------------
__global__ __launch_bounds__(256) void convAll(
    const float* __restrict__ wqkv, const float* __restrict__ wout,
    const float* __restrict__ w1,   const float* __restrict__ w3,
    const float* __restrict__ w2,
    __half* __restrict__ dqkv, __half* __restrict__ dout,
    __half* __restrict__ d13,  __half* __restrict__ d2)
{
    int gid = blockIdx.x * 256 + threadIdx.x;
    const float* src; __half* dst; int K, mstep, moff;
    if (gid < 3145728)       { src = wqkv; dst = dqkv; K = DD; mstep = 1; moff = 0; }
    else if (gid < 4194304)  { src = wout; dst = dout; K = DD; mstep = 1; moff = 0; gid -= 3145728; }
    else if (gid < 8388608)  { src = w1;   dst = d13;  K = DD; mstep = 2; moff = 0; gid -= 4194304; }
    else if (gid < 12582912) { src = w3;   dst = d13;  K = DD; mstep = 2; moff = 1; gid -= 8388608; }
    else                     { src = w2;   dst = d2;   K = FF; mstep = 1; moff = 0; gid -= 12582912; }
    const int kq = K >> 2;
    const int m  = gid / kq;
    const int k  = (gid - m * kq) << 2;
    float4 v = *(const float4*)(src + (size_t)m * K + k);
    pack4H((char*)dst, K >> 6, m * mstep + moff, k, v);
}

// ---------------- fp16 mma.sync GEMM (unchanged, proven) ------------------------
#define G_STG    3
#define G_TB     16384
#define G_SMEM   (1024 + G_STG*2*G_TB)        // 99328
#define GROUP_M  8

__global__ __launch_bounds__(288, 2) void gemm_mma(
    const __half* __restrict__ A2, const __half* __restrict__ B2,
    const float* __restrict__ bias, const float* __restrict__ bias3,
    const float* __restrict__ E,
    float* __restrict__ C, __half* __restrict__ P, __half* __restrict__ Hrow,
    int N, int ktK, int mode)
{
    extern __shared__ char sm[];
    const uint32_t sb = smem_u32(sm);
    const int tid = threadIdx.x, wid = tid >> 5, lane = tid & 31;

    const uint32_t MFULL  = sb;
    const uint32_t MEMPTY = sb + 256;
    const uint32_t SA     = sb + 1024;
    const uint32_t SBq    = SA + G_STG * G_TB;

    if (tid == 0) {
        #pragma unroll
        for (int s = 0; s < G_STG; s++) { MBAR_INIT(MFULL + s*8, 1); MBAR_INIT(MEMPTY + s*8, 8); }
    }
    __syncthreads();

    const int gridN = gridDim.x;
    const int bid   = blockIdx.y * gridN + blockIdx.x;
    const int tpg   = GROUP_M * gridN;
    const int grp   = bid / tpg, rem = bid - grp * tpg;
    const int mt    = grp * GROUP_M + (rem % GROUP_M);
    const int nt    = rem / GROUP_M;

    float d[2][8][4];
    #pragma unroll
    for (int a = 0; a < 2; a++)
        #pragma unroll
        for (int b = 0; b < 8; b++)
            #pragma unroll
            for (int c = 0; c < 4; c++) d[a][b][c] = 0.f;

    if (wid == 8) {
        if (elect_one()) {
            const char* Ag = (const char*)A2 + (size_t)mt * ktK * G_TB;
            const char* Bg = (const char*)B2 + (size_t)nt * ktK * G_TB;
            int s = 0, ph = 1;
            for (int kt = 0; kt < ktK; kt++) {
                MBAR_WAIT(MEMPTY + s*8, ph);
                MBAR_EXPECT(MFULL + s*8, 2*G_TB);
                BULK_G2S(SA  + s*G_TB, Ag + (size_t)kt*G_TB, G_TB, MFULL + s*8);
                BULK_G2S(SBq + s*G_TB, Bg + (size_t)kt*G_TB, G_TB, MFULL + s*8);
                if (++s == G_STG) { s = 0; ph ^= 1; }
            }
        }
    } else {
        const int wm = (wid & 3) * 32;
        const int wn = (wid >> 2) * 64;
        const uint32_t rsub   = (uint32_t)(((lane >> 3) & 1) * 8 + (lane & 7));
        const uint32_t ksel   = (uint32_t)((lane >> 4) * 16);
        const uint32_t cmask  = (uint32_t)((lane & 7) << 4);
        const uint32_t aRowOff = (uint32_t)(wm + rsub) * 128;
        const uint32_t bRowOff = (uint32_t)(wn + rsub) * 128;

        int s = 0, ph = 0;
        for (int kt = 0; kt < ktK; kt++) {
            MBAR_WAIT(MFULL + s*8, ph);
            const uint32_t sa  = SA  + s*G_TB;
            const uint32_t sbb = SBq + s*G_TB;
            #pragma unroll
            for (int kk4 = 0; kk4 < 4; kk4++) {
                const uint32_t ko = (uint32_t)(kk4*32 + ksel) ^ cmask;
                uint32_t af[2][4];
                #pragma unroll
                for (int mi = 0; mi < 2; mi++)
                    LDSM_X4(af[mi][0], af[mi][1], af[mi][2], af[mi][3],
                            sa + aRowOff + mi*2048 + ko);
                uint32_t bf[8][2];
                #pragma unroll
                for (int ng = 0; ng < 4; ng++) {
                    uint32_t t0, t1, t2, t3;
                    LDSM_X4(t0, t1, t2, t3, sbb + bRowOff + ng*2048 + ko);
                    bf[2*ng][0] = t0; bf[2*ng+1][0] = t1;
                    bf[2*ng][1] = t2; bf[2*ng+1][1] = t3;
                }
                #pragma unroll
                for (int mi = 0; mi < 2; mi++)
                    #pragma unroll
                    for (int ni = 0; ni < 8; ni++)
                        MMA16816H(d[mi][ni], af[mi], bf[ni]);
            }
            if (lane == 0) MBAR_ARRIVE(MEMPTY + s*8);
            if (++s == G_STG) { s = 0; ph ^= 1; }
        }
    }

    __syncthreads();

    float* st = (float*)(sm + 1024);
    if (wid < 8) {
        const int wm = (wid & 3) * 32;
        const int wn = (wid >> 2) * 64;
        const int r0 = lane >> 2;
        const int cc = (lane & 3) * 2;
        #pragma unroll
        for (int mi = 0; mi < 2; mi++)
            #pragma unroll
            for (int ni = 0; ni < 8; ni++) {
                const int r = wm + mi*16 + r0;
                const int c = wn + ni*8 + cc;
                st[r*132 + c]       = d[mi][ni][0];
                st[r*132 + c + 1]   = d[mi][ni][1];
                st[(r+8)*132 + c]   = d[mi][ni][2];
                st[(r+8)*132 + c+1] = d[mi][ni][3];
            }
    }
    __syncthreads();

    if (mode == 3) {
        if (tid < 256) {
            const int r0 = tid >> 4;
            const int cg = (tid & 15) * 4;
            const int nG = nt*64 + cg;
            float4 b1v = *(const float4*)(bias  + nG);
            float4 b3v = *(const float4*)(bias3 + nG);
            #pragma unroll 4
            for (int rp = 0; rp < 8; rp++) {
                const int r = rp*16 + r0;
                float4 u0 = *(float4*)&st[r*132 + cg*2];
                float4 u1 = *(float4*)&st[r*132 + cg*2 + 4];
                float4 g;
                g.x = (u0.x + b1v.x) + fmaxf(u0.y + b3v.x, 0.f);
                g.y = (u0.z + b1v.y) + fmaxf(u0.w + b3v.y, 0.f);
                g.z = (u1.x + b1v.z) + fmaxf(u1.y + b3v.z, 0.f);
                g.w = (u1.z + b1v.w) + fmaxf(u1.w + b3v.w, 0.f);
                pack4H((char*)P, FF/64, mt*128 + r, nG, g);
            }
        }
    } else if (tid < 256) {
        const int r0 = tid >> 5;
        const int c  = (tid & 31) * 4;
        const int n  = nt*128 + c;
        float4 bv = make_float4(0.f, 0.f, 0.f, 0.f);
        if (bias) bv = *(const float4*)(bias + n);
        #pragma unroll 4
        for (int rp = 0; rp < 16; rp++) {
            const int r = rp*8 + r0;
            const size_t idx = (size_t)(mt*128 + r) * N + n;
            float4 v = *(float4*)&st[r*132 + c];
            v.x += bv.x; v.y += bv.y; v.z += bv.z; v.w += bv.w;
            if (mode == 2) {
                float4 e = *(const float4*)(E + idx);
                v.x += e.x; v.y += e.y; v.z += e.z; v.w += e.w;
            }
            if (P)         pack4H((char*)P, N >> 6, mt*128 + r, n, v);
            else if (Hrow) *(uint2*)(Hrow + idx) = make_uint2(h2pack(v.x, v.y), h2pack(v.z, v.w));
            else           *(float4*)(C + idx) = v;
        }
    }
}

// ---------------- fp16 flash attention: Br=128, scores/P in registers -----------
// smem: K0 @0, K1 @16384, V0 @32768, V1 @49152  (Q staged in K1/V1 at prologue)
#define AT_SMEM 65536
#define ASCALE  0.08838834764831845f

__global__ __launch_bounds__(256, 1) void attn_fp16(
    const __half* __restrict__ qkvh, __half* __restrict__ outP)
{
    extern __shared__ char smc[];
    const uint32_t sb = smem_u32(smc);
    const int tid = threadIdx.x, wid = tid >> 5, lane = tid & 31;
    const int qt = (int)gridDim.x - 1 - (int)blockIdx.x;   // longest CTAs first
    const int hh = blockIdx.y, bb = blockIdx.z;
    const int q0 = qt * 128;

    // ---- prologue: Q (128x128) staged into K1/V1 regions; K0/V0 for jt=0
    #pragma unroll
    for (int i = 0; i < 8; i++) {
        const int id = i*256 + tid;              // 0..2047
        const int rr = id >> 4, oc = id & 15;
        uint32_t off = (uint32_t)(rr*128 + (oc & 7)*16);
        off ^= (off >> 3) & 0x70;
        const uint32_t dst = (oc >> 3) ? 49152u : 16384u;
        *(uint4*)(smc + dst + off) =
            *(const uint4*)(qkvh + (size_t)(bb*SS + q0 + rr) * QKVW + hh*HD + oc*8);
    }
    #pragma unroll
    for (int i = 0; i < 4; i++) {
        const int id = i*256 + tid;              // 0..1023
        const int rr = id >> 4, oc = id & 15;
        uint32_t off = (uint32_t)(rr*128 + (oc & 7)*16);
        off ^= (off >> 3) & 0x70;
        const uint32_t toff = (uint32_t)(oc >> 3)*8192 + off;
        const __half* base = qkvh + (size_t)(bb*SS + rr) * QKVW + hh*HD + oc*8;
        *(uint4*)(smc + toff)         = *(const uint4*)(base + 16*HD);   // K0
        *(uint4*)(smc + 32768 + toff) = *(const uint4*)(base + 32*HD);   // V0
    }
    __syncthreads();

    const int wm = wid * 16;
    const uint32_t rsub  = (uint32_t)(((lane >> 3) & 1) * 8 + (lane & 7));
    const uint32_t ksel  = (uint32_t)((lane >> 4) * 16);
    const uint32_t cmask = (uint32_t)((lane & 7) << 4);
    const uint32_t aRowOff = (uint32_t)(wm + rsub) * 128;

    // ---- Q a-fragments into registers (8 k-steps of 16)
    uint32_t qf[8][4];
    #pragma unroll
    for (int ks = 0; ks < 8; ks++) {
        const uint32_t qbase = (ks < 4) ? 16384u : 49152u;
        const uint32_t ko = (uint32_t)((ks & 3)*32 + ksel) ^ cmask;
        LDSM_X4(qf[ks][0], qf[ks][1], qf[ks][2], qf[ks][3], sb + qbase + aRowOff + ko);
    }
    __syncthreads();   // all Q reads done before K1/V1 overwritten

    const int r0l = lane >> 2;
    const int rA0 = wm + r0l, rA1 = rA0 + 8;   // q-local rows
    const int cc  = (lane & 3) * 2;
    const int vrow = lane & 15;
    const int voct = lane >> 4;

    float mrun0 = -INFINITY, mrun1 = -INFINITY, lrun0 = 0.f, lrun1 = 0.f;
    float o[16][4];
    #pragma unroll
    for (int i = 0; i < 16; i++)
        #pragma unroll
        for (int j = 0; j < 4; j++) o[i][j] = 0.f;

    const int njt = 2*qt + 2;
    for (int jt = 0; jt < njt; jt++) {
        const int cur = jt & 1;
        const uint32_t kb = sb + (uint32_t)cur*16384;
        const uint32_t vb = sb + 32768 + (uint32_t)cur*16384;
        const int j0 = jt * 64;

        // prefetch next K/V into registers
        uint4 kreg[4], vreg[4];
        const bool hn = (jt + 1 < njt);
        if (hn) {
            #pragma unroll
            for (int i = 0; i < 4; i++) {
                const int id = i*256 + tid;
                const int rr = id >> 4, oc = id & 15;
                const __half* base = qkvh + (size_t)(bb*SS + j0 + 64 + rr) * QKVW + hh*HD + oc*8;
                kreg[i] = *(const uint4*)(base + 16*HD);
                vreg[i] = *(const uint4*)(base + 32*HD);
            }
        }

        // ---- QK^T: 16x64 scores per warp, all in registers
        float c[8][4];
        #pragma unroll
        for (int i = 0; i < 8; i++)
            #pragma unroll
            for (int j = 0; j < 4; j++) c[i][j] = 0.f;
        #pragma unroll
        for (int ks = 0; ks < 8; ks++) {
            const uint32_t ko = (uint32_t)((ks & 3)*32 + ksel) ^ cmask;
            const uint32_t kt = kb + (uint32_t)(ks >> 2)*8192;
            #pragma unroll
            for (int ng = 0; ng < 4; ng++) {
                uint32_t t0, t1, t2, t3;
                LDSM_X4(t0, t1, t2, t3, kt + (uint32_t)(ng*16 + rsub)*128 + ko);
                uint32_t b0[2] = {t0, t2};
                uint32_t b1[2] = {t1, t3};
                MMA16816H(c[2*ng],   qf[ks], b0);
                MMA16816H(c[2*ng+1], qf[ks], b1);
            }
        }

        // ---- register softmax (rows = 4-lane shfl groups)
        const int lim0 = q0 + rA0 - j0;
        const int lim1 = lim0 + 8;
        float mx0 = -INFINITY, mx1 = -INFINITY;
        #pragma unroll
        for (int t = 0; t < 8; t++) {
            const int col = t*8 + cc;
            c[t][0] = (col     > lim0) ? -INFINITY : c[t][0]*ASCALE;
            c[t][1] = (col + 1 > lim0) ? -INFINITY : c[t][1]*ASCALE;
            c[t][2] = (col     > lim1) ? -INFINITY : c[t][2]*ASCALE;
            c[t][3] = (col + 1 > lim1) ? -INFINITY : c[t][3]*ASCALE;
            mx0 = fmaxf(mx0, fmaxf(c[t][0], c[t][1]));
            mx1 = fmaxf(mx1, fmaxf(c[t][2], c[t][3]));
        }
        mx0 = fmaxf(mx0, __shfl_xor_sync(0xffffffffu, mx0, 1));
        mx0 = fmaxf(mx0, __shfl_xor_sync(0xffffffffu, mx0, 2));
        mx1 = fmaxf(mx1, __shfl_xor_sync(0xffffffffu, mx1, 1));
        mx1 = fmaxf(mx1, __shfl_xor_sync(0xffffffffu, mx1, 2));
        const float mN0 = fmaxf(mrun0, mx0), mN1 = fmaxf(mrun1, mx1);
        const float cor0 = __expf(mrun0 - mN0), cor1 = __expf(mrun1 - mN1);
        float ls0 = 0.f, ls1 = 0.f;
        uint32_t pf[4][4];
        #pragma unroll
        for (int t = 0; t < 8; t++) {
            float p0 = (c[t][0] == -INFINITY) ? 0.f : __expf(c[t][0] - mN0);
            float p1 = (c[t][1] == -INFINITY) ? 0.f : __expf(c[t][1] - mN0);
            float p2 = (c[t][2] == -INFINITY) ? 0.f : __expf(c[t][2] - mN1);
            float p3 = (c[t][3] == -INFINITY) ? 0.f : __expf(c[t][3] - mN1);
            ls0 += p0 + p1; ls1 += p2 + p3;
            if ((t & 1) == 0) { pf[t>>1][0] = h2pack(p0, p1); pf[t>>1][1] = h2pack(p2, p3); }
            else              { pf[t>>1][2] = h2pack(p0, p1); pf[t>>1][3] = h2pack(p2, p3); }
        }
        ls0 += __shfl_xor_sync(0xffffffffu, ls0, 1);
        ls0 += __shfl_xor_sync(0xffffffffu, ls0, 2);
        ls1 += __shfl_xor_sync(0xffffffffu, ls1, 1);
        ls1 += __shfl_xor_sync(0xffffffffu, ls1, 2);
        lrun0 = lrun0 * cor0 + ls0;
        lrun1 = lrun1 * cor1 + ls1;
        mrun0 = mN0; mrun1 = mN1;

        #pragma unroll
        for (int i = 0; i < 16; i++) {
            o[i][0] *= cor0; o[i][1] *= cor0;
            o[i][2] *= cor1; o[i][3] *= cor1;
        }

        // ---- store prefetched K/V into alternate buffers
        if (hn) {
            const uint32_t koff = (uint32_t)(cur ^ 1)*16384;
            const uint32_t voff = 32768 + (uint32_t)(cur ^ 1)*16384;
            #pragma unroll
            for (int i = 0; i < 4; i++) {
                const int id = i*256 + tid;
                const int rr = id >> 4, oc = id & 15;
                uint32_t off = (uint32_t)(rr*128 + (oc & 7)*16);
                off ^= (off >> 3) & 0x70;
                const uint32_t toff = (uint32_t)(oc >> 3)*8192 + off;
                *(uint4*)(smc + koff + toff) = kreg[i];
                *(uint4*)(smc + voff + toff) = vreg[i];
            }
        }

        // ---- PV: P a-frags direct from registers; V via ldmatrix.trans
        #pragma unroll
        for (int kp = 0; kp < 4; kp++) {
            const int row = kp*16 + vrow;
            const uint32_t rkey = (uint32_t)((row & 7) << 4);
            #pragma unroll
            for (int t = 0; t < 2; t++) {
                const uint32_t vt = vb + (uint32_t)t*8192;
                #pragma unroll
                for (int p = 0; p < 4; p++) {
                    const uint32_t bcol = (uint32_t)(p*32 + voct*16) ^ rkey;
                    uint32_t t0, t1, t2, t3;
                    LDSM_X4T(t0, t1, t2, t3, vt + (uint32_t)row*128 + bcol);
                    uint32_t b0[2] = {t0, t1};
                    uint32_t b1[2] = {t2, t3};
                    MMA16816H(o[t*8 + p*2],     pf[kp], b0);
                    MMA16816H(o[t*8 + p*2 + 1], pf[kp], b1);
                }
            }
        }
        __syncthreads();   // buffers safe for next iteration
    }

    // ---- normalize + packed store (raw-reshape [B*S, D] mapping)
    {
        const float inv0 = 1.f / lrun0;
        const float inv1 = 1.f / lrun1;
        const int t0i = (bb*HH + hh)*SS + q0 + rA0;
        const int t1i = (bb*HH + hh)*SS + q0 + rA1;
        const int m0 = t0i >> 4, cB0 = (t0i & 15) * 128;
        const int m1 = t1i >> 4, cB1 = (t1i & 15) * 128;
        #pragma unroll
        for (int ntl = 0; ntl < 16; ntl++) {
            const int cb = ntl*8 + cc;
            pack2H((char*)outP, DD/64, m0, cB0 + cb, o[ntl][0]*inv0, o[ntl][1]*inv0);
            pack2H((char*)outP, DD/64, m1, cB1 + cb, o[ntl][2]*inv1, o[ntl][3]*inv1);
        }
    }
}

// ---------------- launch --------------------------------------------------------
extern "C" void kernel_launch(void* const* d_in, const int* in_sizes, int n_in,
                              void* d_out, int out_size)
{
    (void)in_sizes; (void)n_in; (void)out_size;
    const float* x     = (const float*)d_in[0];
    const float* rms_w = (const float*)d_in[1];
    const float* w_qkv = (const float*)d_in[2];
    const float* w_out = (const float*)d_in[3];
    const float* w1    = (const float*)d_in[4];
    const float* b1    = (const float*)d_in[5];
    const float* w3    = (const float*)d_in[6];
    const float* b3    = (const float*)d_in[7];
    const float* w2    = (const float*)d_in[8];
    const float* b2    = (const float*)d_in[9];
    float* out = (float*)d_out;

    __half *qkvh,*xn2,*att2,*h2,*gg2,*wqkv2,*wout2,*w132,*w22;
    cudaGetSymbolAddress((void**)&qkvh,  g_qkvh);
    cudaGetSymbolAddress((void**)&xn2,   g_xn2);
    cudaGetSymbolAddress((void**)&att2,  g_att2);
    cudaGetSymbolAddress((void**)&h2,    g_h2);
    cudaGetSymbolAddress((void**)&gg2,   g_gg2);
    cudaGetSymbolAddress((void**)&wqkv2, g_wqkv2);
    cudaGetSymbolAddress((void**)&wout2, g_wout2);
    cudaGetSymbolAddress((void**)&w132,  g_w132);
    cudaGetSymbolAddress((void**)&w22,   g_w22);

    cudaFuncSetAttribute(gemm_mma, cudaFuncAttributeMaxDynamicSharedMemorySize, G_SMEM);
    cudaFuncSetAttribute(attn_fp16, cudaFuncAttributeMaxDynamicSharedMemorySize, AT_SMEM);

    // all weight conversions in one launch
    convAll<<<65536, 256>>>(w_qkv, w_out, w1, w3, w2, wqkv2, wout2, w132, w22);

    // 1) RMSNorm -> packed
    rmsnorm_pack<<<MM, 256>>>(x, rms_w, xn2);

    // 2) QKV projection -> fp16 row-major
    gemm_mma<<<dim3(QKVW/128, MM/128), 288, G_SMEM>>>(
        xn2, wqkv2, nullptr, nullptr, nullptr, nullptr, nullptr, qkvh, QKVW, DD/64, 0);

    // 3) attention (Br=128, register softmax/P) -> packed att2
    attn_fp16<<<dim3(SS/128, HH, BB), 256, AT_SMEM>>>(qkvh, att2);

    // 4) out projection -> packed h2
    gemm_mma<<<dim3(DD/128, MM/128), 288, G_SMEM>>>(
        att2, wout2, nullptr, nullptr, nullptr, nullptr, h2, nullptr, DD, DD/64, 0);

    // 5+6) fused dual-FFN: gg = (h@w1^T + b1) + relu(h@w3^T + b3) -> packed gg2
    gemm_mma<<<dim3(2*FF/128, MM/128), 288, G_SMEM>>>(
        h2, w132, b1, b3, nullptr, nullptr, gg2, nullptr, 2*FF, DD/64, 3);

    // 7) out = x + gg @ w2^T + b2 (fp32 final)
    gemm_mma<<<dim3(DD/128, MM/128), 288, G_SMEM>>>(
        gg2, w22, b2, nullptr, x, out, nullptr, nullptr, DD, FF/64, 2);
}

// round 14
// speedup vs baseline: 1.2873x; 1.2873x over previous
#include <cuda_runtime.h>
#include <cuda_fp16.h>
#include <math.h>
#include <stdint.h>

#define BB   2
#define SS   2048
#define DD   2048
#define HH   16
#define HD   128
#define FF   8192
#define MM   (BB*SS)          // 4096
#define QKVW (3*DD)           // 6144

// ---------------- scratch ----------------
__device__ __half g_qkvh[(size_t)MM*QKVW];     // fp16 row-major qkv
// fp16 packed (tiled [rows/128][K/64][128][64], SW128)
__device__ __half g_xn2 [(size_t)MM*DD];
__device__ __half g_att2[(size_t)MM*DD];
__device__ __half g_h2  [(size_t)MM*DD];
__device__ __half g_gg2 [(size_t)MM*FF];
__device__ __half g_wqkv2[(size_t)QKVW*DD];
__device__ __half g_wout2[(size_t)DD*DD];
__device__ __half g_w132[(size_t)2*FF*DD];     // w1/w3 row-interleaved
__device__ __half g_w22 [(size_t)DD*FF];

// ---------------- PTX helpers -------------------------------------------------
__device__ __forceinline__ uint32_t smem_u32(const void* p) {
    uint32_t a;
    asm("{ .reg .u64 t; cvta.to.shared.u64 t, %1; cvt.u32.u64 %0, t; }" : "=r"(a) : "l"(p));
    return a;
}
__device__ __forceinline__ uint32_t elect_one() {
    uint32_t p;
    asm volatile("{ .reg .pred p; elect.sync _|p, 0xFFFFFFFF; selp.b32 %0,1,0,p; }" : "=r"(p));
    return p;
}
#define MBAR_INIT(a, c) \
    asm volatile("mbarrier.init.shared.b64 [%0], %1;" :: "r"(a), "r"(c) : "memory")
#define MBAR_EXPECT(a, b) \
    asm volatile("mbarrier.arrive.expect_tx.shared.b64 _, [%0], %1;" :: "r"(a), "r"(b) : "memory")
#define MBAR_ARRIVE(a) \
    asm volatile("mbarrier.arrive.shared.b64 _, [%0];" :: "r"(a) : "memory")
#define MBAR_WAIT(a, ph) do { uint32_t _m=(a), _p=(ph), _d;                                   \
    asm volatile("{ .reg .pred p; mbarrier.try_wait.parity.acquire.cta.shared::cta.b64 p, [%1], %2; selp.b32 %0,1,0,p; }" \
                 : "=r"(_d) : "r"(_m), "r"(_p) : "memory");                                   \
    if (!_d) {                                                                                \
      asm volatile("{ .reg .pred P1; WL%=: mbarrier.try_wait.parity.acquire.cta.shared::cta.b64 P1, [%0], %1, 0x989680; @P1 bra.uni WD%=; bra.uni WL%=; WD%=: }" \
                   :: "r"(_m), "r"(_p) : "memory"); } } while(0)
#define BULK_G2S(d, s, n, m) \
    asm volatile("cp.async.bulk.shared::cta.global.mbarrier::complete_tx::bytes [%0], [%1], %2, [%3];" \
                 :: "r"(d), "l"(s), "r"(n), "r"(m) : "memory")
#define LDSM_X4(r0, r1, r2, r3, a) \
    asm volatile("ldmatrix.sync.aligned.m8n8.x4.shared.b16 {%0,%1,%2,%3}, [%4];" \
                 : "=r"(r0), "=r"(r1), "=r"(r2), "=r"(r3) : "r"(a))
#define LDSM_X4T(r0, r1, r2, r3, a) \
    asm volatile("ldmatrix.sync.aligned.m8n8.x4.trans.shared.b16 {%0,%1,%2,%3}, [%4];" \
                 : "=r"(r0), "=r"(r1), "=r"(r2), "=r"(r3) : "r"(a))
#define MMA16816H(d, av, bv) \
    asm volatile("mma.sync.aligned.m16n8k16.row.col.f32.f16.f16.f32 " \
                 "{%0,%1,%2,%3}, {%4,%5,%6,%7}, {%8,%9}, {%0,%1,%2,%3};" \
                 : "+f"((d)[0]), "+f"((d)[1]), "+f"((d)[2]), "+f"((d)[3]) \
                 : "r"((av)[0]), "r"((av)[1]), "r"((av)[2]), "r"((av)[3]), \
                   "r"((bv)[0]), "r"((bv)[1]))

// ---------------- fp16 pack helpers --------------------------------------------
__device__ __forceinline__ uint32_t h2pack(float v0, float v1) {
    return (uint32_t)__half_as_ushort(__float2half_rn(v0))
         | ((uint32_t)__half_as_ushort(__float2half_rn(v1)) << 16);
}
__device__ __forceinline__ void pack4H(char* base, int ktK, int m, int n, float4 v) {
    const int mt = m >> 7, mr = m & 127;
    const int kt = n >> 6, c = n & 63;
    const size_t tb = ((size_t)mt * ktK + kt) * 16384;
    uint32_t off = (uint32_t)(mr * 128 + c * 2);
    off ^= (off >> 3) & 0x70;
    *(uint2*)(base + tb + off) = make_uint2(h2pack(v.x, v.y), h2pack(v.z, v.w));
}
__device__ __forceinline__ void pack2H(char* base, int ktK, int m, int n, float v0, float v1) {
    const int mt = m >> 7, mr = m & 127;
    const int kt = n >> 6, c = n & 63;
    const size_t tb = ((size_t)mt * ktK + kt) * 16384;
    uint32_t off = (uint32_t)(mr * 128 + c * 2);
    off ^= (off >> 3) & 0x70;
    *(uint32_t*)(base + tb + off) = h2pack(v0, v1);
}

// ---------------- RMSNorm -> packed fp16 ---------------------------------------
__global__ __launch_bounds__(256) void rmsnorm_pack(
    const float* __restrict__ x, const float* __restrict__ w, __half* __restrict__ dst)
{
    const int row = blockIdx.x;
    const float4* xr = (const float4*)(x + (size_t)row * DD);
    float4 a = xr[threadIdx.x];
    float4 b = xr[threadIdx.x + 256];
    float ss = a.x*a.x + a.y*a.y + a.z*a.z + a.w*a.w
             + b.x*b.x + b.y*b.y + b.z*b.z + b.w*b.w;
    #pragma unroll
    for (int o = 16; o; o >>= 1) ss += __shfl_xor_sync(0xffffffffu, ss, o);
    __shared__ float sred[8];
    if ((threadIdx.x & 31) == 0) sred[threadIdx.x >> 5] = ss;
    __syncthreads();
    float tot = sred[0]+sred[1]+sred[2]+sred[3]+sred[4]+sred[5]+sred[6]+sred[7];
    float sc = rsqrtf(tot * (1.0f / DD) + 1e-5f);

    const float4* wr = (const float4*)w;
    #pragma unroll
    for (int g = 0; g < 2; g++) {
        const int gi = threadIdx.x + g*256;
        float4 v = (g == 0) ? a : b;
        float4 wv = wr[gi];
        v.x *= sc * wv.x; v.y *= sc * wv.y; v.z *= sc * wv.z; v.w *= sc * wv.w;
        pack4H((char*)dst, DD/64, row, gi*4, v);
    }
}

// ---------------- all weight conversions in ONE launch --------------------------
__global__ __launch_bounds__(256) void convAll(
    const float* __restrict__ wqkv, const float* __restrict__ wout,
    const float* __restrict__ w1,   const float* __restrict__ w3,
    const float* __restrict__ w2,
    __half* __restrict__ dqkv, __half* __restrict__ dout,
    __half* __restrict__ d13,  __half* __restrict__ d2)
{
    int gid = blockIdx.x * 256 + threadIdx.x;
    const float* src; __half* dst; int K, mstep, moff;
    if (gid < 3145728)       { src = wqkv; dst = dqkv; K = DD; mstep = 1; moff = 0; }
    else if (gid < 4194304)  { src = wout; dst = dout; K = DD; mstep = 1; moff = 0; gid -= 3145728; }
    else if (gid < 8388608)  { src = w1;   dst = d13;  K = DD; mstep = 2; moff = 0; gid -= 4194304; }
    else if (gid < 12582912) { src = w3;   dst = d13;  K = DD; mstep = 2; moff = 1; gid -= 8388608; }
    else                     { src = w2;   dst = d2;   K = FF; mstep = 1; moff = 0; gid -= 12582912; }
    const int kq = K >> 2;
    const int m  = gid / kq;
    const int k  = (gid - m * kq) << 2;
    float4 v = *(const float4*)(src + (size_t)m * K + k);
    pack4H((char*)dst, K >> 6, m * mstep + moff, k, v);
}

// ---------------- fp16 mma.sync GEMM (round-12 proven) --------------------------
#define G_STG    3
#define G_TB     16384
#define G_SMEM   (1024 + G_STG*2*G_TB)        // 99328
#define GROUP_M  8

__global__ __launch_bounds__(288, 2) void gemm_mma(
    const __half* __restrict__ A2, const __half* __restrict__ B2,
    const float* __restrict__ bias, const float* __restrict__ bias3,
    const float* __restrict__ E,
    float* __restrict__ C, __half* __restrict__ P, __half* __restrict__ Hrow,
    int N, int ktK, int mode)
{
    extern __shared__ char sm[];
    const uint32_t sb = smem_u32(sm);
    const int tid = threadIdx.x, wid = tid >> 5, lane = tid & 31;

    const uint32_t MFULL  = sb;
    const uint32_t MEMPTY = sb + 256;
    const uint32_t SA     = sb + 1024;
    const uint32_t SBq    = SA + G_STG * G_TB;

    if (tid == 0) {
        #pragma unroll
        for (int s = 0; s < G_STG; s++) { MBAR_INIT(MFULL + s*8, 1); MBAR_INIT(MEMPTY + s*8, 8); }
    }
    __syncthreads();

    const int gridN = gridDim.x;
    const int bid   = blockIdx.y * gridN + blockIdx.x;
    const int tpg   = GROUP_M * gridN;
    const int grp   = bid / tpg, rem = bid - grp * tpg;
    const int mt    = grp * GROUP_M + (rem % GROUP_M);
    const int nt    = rem / GROUP_M;

    float d[2][8][4];
    #pragma unroll
    for (int a = 0; a < 2; a++)
        #pragma unroll
        for (int b = 0; b < 8; b++)
            #pragma unroll
            for (int c = 0; c < 4; c++) d[a][b][c] = 0.f;

    if (wid == 8) {
        if (elect_one()) {
            const char* Ag = (const char*)A2 + (size_t)mt * ktK * G_TB;
            const char* Bg = (const char*)B2 + (size_t)nt * ktK * G_TB;
            int s = 0, ph = 1;
            for (int kt = 0; kt < ktK; kt++) {
                MBAR_WAIT(MEMPTY + s*8, ph);
                MBAR_EXPECT(MFULL + s*8, 2*G_TB);
                BULK_G2S(SA  + s*G_TB, Ag + (size_t)kt*G_TB, G_TB, MFULL + s*8);
                BULK_G2S(SBq + s*G_TB, Bg + (size_t)kt*G_TB, G_TB, MFULL + s*8);
                if (++s == G_STG) { s = 0; ph ^= 1; }
            }
        }
    } else {
        const int wm = (wid & 3) * 32;
        const int wn = (wid >> 2) * 64;
        const uint32_t rsub   = (uint32_t)(((lane >> 3) & 1) * 8 + (lane & 7));
        const uint32_t ksel   = (uint32_t)((lane >> 4) * 16);
        const uint32_t cmask  = (uint32_t)((lane & 7) << 4);
        const uint32_t aRowOff = (uint32_t)(wm + rsub) * 128;
        const uint32_t bRowOff = (uint32_t)(wn + rsub) * 128;

        int s = 0, ph = 0;
        for (int kt = 0; kt < ktK; kt++) {
            MBAR_WAIT(MFULL + s*8, ph);
            const uint32_t sa  = SA  + s*G_TB;
            const uint32_t sbb = SBq + s*G_TB;
            #pragma unroll
            for (int kk4 = 0; kk4 < 4; kk4++) {
                const uint32_t ko = (uint32_t)(kk4*32 + ksel) ^ cmask;
                uint32_t af[2][4];
                #pragma unroll
                for (int mi = 0; mi < 2; mi++)
                    LDSM_X4(af[mi][0], af[mi][1], af[mi][2], af[mi][3],
                            sa + aRowOff + mi*2048 + ko);
                uint32_t bf[8][2];
                #pragma unroll
                for (int ng = 0; ng < 4; ng++) {
                    uint32_t t0, t1, t2, t3;
                    LDSM_X4(t0, t1, t2, t3, sbb + bRowOff + ng*2048 + ko);
                    bf[2*ng][0] = t0; bf[2*ng+1][0] = t1;
                    bf[2*ng][1] = t2; bf[2*ng+1][1] = t3;
                }
                #pragma unroll
                for (int mi = 0; mi < 2; mi++)
                    #pragma unroll
                    for (int ni = 0; ni < 8; ni++)
                        MMA16816H(d[mi][ni], af[mi], bf[ni]);
            }
            if (lane == 0) MBAR_ARRIVE(MEMPTY + s*8);
            if (++s == G_STG) { s = 0; ph ^= 1; }
        }
    }

    __syncthreads();

    float* st = (float*)(sm + 1024);
    if (wid < 8) {
        const int wm = (wid & 3) * 32;
        const int wn = (wid >> 2) * 64;
        const int r0 = lane >> 2;
        const int cc = (lane & 3) * 2;
        #pragma unroll
        for (int mi = 0; mi < 2; mi++)
            #pragma unroll
            for (int ni = 0; ni < 8; ni++) {
                const int r = wm + mi*16 + r0;
                const int c = wn + ni*8 + cc;
                st[r*132 + c]       = d[mi][ni][0];
                st[r*132 + c + 1]   = d[mi][ni][1];
                st[(r+8)*132 + c]   = d[mi][ni][2];
                st[(r+8)*132 + c+1] = d[mi][ni][3];
            }
    }
    __syncthreads();

    if (mode == 3) {
        if (tid < 256) {
            const int r0 = tid >> 4;
            const int cg = (tid & 15) * 4;
            const int nG = nt*64 + cg;
            float4 b1v = *(const float4*)(bias  + nG);
            float4 b3v = *(const float4*)(bias3 + nG);
            #pragma unroll 4
            for (int rp = 0; rp < 8; rp++) {
                const int r = rp*16 + r0;
                float4 u0 = *(float4*)&st[r*132 + cg*2];
                float4 u1 = *(float4*)&st[r*132 + cg*2 + 4];
                float4 g;
                g.x = (u0.x + b1v.x) + fmaxf(u0.y + b3v.x, 0.f);
                g.y = (u0.z + b1v.y) + fmaxf(u0.w + b3v.y, 0.f);
                g.z = (u1.x + b1v.z) + fmaxf(u1.y + b3v.z, 0.f);
                g.w = (u1.z + b1v.w) + fmaxf(u1.w + b3v.w, 0.f);
                pack4H((char*)P, FF/64, mt*128 + r, nG, g);
            }
        }
    } else if (tid < 256) {
        const int r0 = tid >> 5;
        const int c  = (tid & 31) * 4;
        const int n  = nt*128 + c;
        float4 bv = make_float4(0.f, 0.f, 0.f, 0.f);
        if (bias) bv = *(const float4*)(bias + n);
        #pragma unroll 4
        for (int rp = 0; rp < 16; rp++) {
            const int r = rp*8 + r0;
            const size_t idx = (size_t)(mt*128 + r) * N + n;
            float4 v = *(float4*)&st[r*132 + c];
            v.x += bv.x; v.y += bv.y; v.z += bv.z; v.w += bv.w;
            if (mode == 2) {
                float4 e = *(const float4*)(E + idx);
                v.x += e.x; v.y += e.y; v.z += e.z; v.w += e.w;
            }
            if (P)         pack4H((char*)P, N >> 6, mt*128 + r, n, v);
            else if (Hrow) *(uint2*)(Hrow + idx) = make_uint2(h2pack(v.x, v.y), h2pack(v.z, v.w));
            else           *(float4*)(C + idx) = v;
        }
    }
}

// ---------------- fp16 flash attention: 128 threads, full-width warps ------------
// 4 warps x 16 q-rows (Br=64); each warp covers all 64 keys -> softmax/P in regs.
// smem: K tile 16KB @0 (2x [64][64] halfs), V tile 16KB @16384. Q staged in K at prologue.
#define AT_SMEM 32768
#define ASCALE  0.08838834764831845f

__global__ __launch_bounds__(128, 3) void attn_fp16(
    const __half* __restrict__ qkvh, __half* __restrict__ outP)
{
    extern __shared__ char smc[];
    const uint32_t sb = smem_u32(smc);
    const int tid = threadIdx.x, wid = tid >> 5, lane = tid & 31;
    const int qt = (int)gridDim.x - 1 - (int)blockIdx.x;   // longest CTAs first
    const int hh = blockIdx.y, bb = blockIdx.z;
    const int q0 = qt * 64;

    // ---- prologue: stage Q (64x128) into K region, read frags, then release
    #pragma unroll
    for (int i = 0; i < 8; i++) {
        const int id = i*128 + tid;              // 0..1023
        const int rr = id >> 4, oc = id & 15;
        uint32_t off = (uint32_t)(rr*128 + (oc & 7)*16);
        off ^= (off >> 3) & 0x70;
        *(uint4*)(smc + (uint32_t)(oc >> 3)*8192 + off) =
            *(const uint4*)(qkvh + (size_t)(bb*SS + q0 + rr) * QKVW + hh*HD + oc*8);
    }
    __syncthreads();

    const int wm = wid * 16;
    const uint32_t rsub  = (uint32_t)(((lane >> 3) & 1) * 8 + (lane & 7));
    const uint32_t ksel  = (uint32_t)((lane >> 4) * 16);
    const uint32_t cmask = (uint32_t)((lane & 7) << 4);
    const uint32_t aRowOff = (uint32_t)(wm + rsub) * 128;

    uint32_t qf[8][4];
    #pragma unroll
    for (int ks = 0; ks < 8; ks++) {
        const uint32_t ko = (uint32_t)((ks & 3)*32 + ksel) ^ cmask;
        LDSM_X4(qf[ks][0], qf[ks][1], qf[ks][2], qf[ks][3],
                sb + (uint32_t)(ks >> 2)*8192 + aRowOff + ko);
    }

    const int rA0 = wm + (lane >> 2), rA1 = rA0 + 8;
    const int cc  = (lane & 3) * 2;
    const int vrow = lane & 15;
    const int voct = lane >> 4;

    float mrun0 = -INFINITY, mrun1 = -INFINITY, lrun0 = 0.f, lrun1 = 0.f;
    float o[16][4];
    #pragma unroll
    for (int i = 0; i < 16; i++)
        #pragma unroll
        for (int j = 0; j < 4; j++) o[i][j] = 0.f;

    const int njt = qt + 1;
    for (int jt = 0; jt < njt; jt++) {
        const int j0 = jt * 64;

        __syncthreads();   // prior reads (Q frags / prev PV) done before overwrite
        #pragma unroll
        for (int i = 0; i < 8; i++) {
            const int id = i*128 + tid;          // 0..1023
            const int rr = id >> 4, oc = id & 15;
            uint32_t off = (uint32_t)(rr*128 + (oc & 7)*16);
            off ^= (off >> 3) & 0x70;
            const uint32_t toff = (uint32_t)(oc >> 3)*8192 + off;
            const __half* base = qkvh + (size_t)(bb*SS + j0 + rr) * QKVW + hh*HD + oc*8;
            *(uint4*)(smc + toff)         = *(const uint4*)(base + 16*HD);   // K
            *(uint4*)(smc + 16384 + toff) = *(const uint4*)(base + 32*HD);   // V
        }
        __syncthreads();

        // ---- QK^T: 16x64 scores per warp, in registers
        float c[8][4];
        #pragma unroll
        for (int i = 0; i < 8; i++)
            #pragma unroll
            for (int j = 0; j < 4; j++) c[i][j] = 0.f;
        #pragma unroll
        for (int ks = 0; ks < 8; ks++) {
            const uint32_t ko = (uint32_t)((ks & 3)*32 + ksel) ^ cmask;
            const uint32_t kt = sb + (uint32_t)(ks >> 2)*8192;
            #pragma unroll
            for (int ng = 0; ng < 4; ng++) {
                uint32_t t0, t1, t2, t3;
                LDSM_X4(t0, t1, t2, t3, kt + (uint32_t)(ng*16 + rsub)*128 + ko);
                uint32_t b0[2] = {t0, t2};
                uint32_t b1[2] = {t1, t3};
                MMA16816H(c[2*ng],   qf[ks], b0);
                MMA16816H(c[2*ng+1], qf[ks], b1);
            }
        }

        // ---- register softmax (rows = 4-lane shfl groups)
        const int lim0 = q0 + rA0 - j0;
        const int lim1 = lim0 + 8;
        float mx0 = -INFINITY, mx1 = -INFINITY;
        #pragma unroll
        for (int t = 0; t < 8; t++) {
            const int col = t*8 + cc;
            c[t][0] = (col     > lim0) ? -INFINITY : c[t][0]*ASCALE;
            c[t][1] = (col + 1 > lim0) ? -INFINITY : c[t][1]*ASCALE;
            c[t][2] = (col     > lim1) ? -INFINITY : c[t][2]*ASCALE;
            c[t][3] = (col + 1 > lim1) ? -INFINITY : c[t][3]*ASCALE;
            mx0 = fmaxf(mx0, fmaxf(c[t][0], c[t][1]));
            mx1 = fmaxf(mx1, fmaxf(c[t][2], c[t][3]));
        }
        mx0 = fmaxf(mx0, __shfl_xor_sync(0xffffffffu, mx0, 1));
        mx0 = fmaxf(mx0, __shfl_xor_sync(0xffffffffu, mx0, 2));
        mx1 = fmaxf(mx1, __shfl_xor_sync(0xffffffffu, mx1, 1));
        mx1 = fmaxf(mx1, __shfl_xor_sync(0xffffffffu, mx1, 2));
        const float mN0 = fmaxf(mrun0, mx0), mN1 = fmaxf(mrun1, mx1);
        const float cor0 = __expf(mrun0 - mN0), cor1 = __expf(mrun1 - mN1);
        float ls0 = 0.f, ls1 = 0.f;
        uint32_t pf[4][4];
        #pragma unroll
        for (int t = 0; t < 8; t++) {
            float p0 = (c[t][0] == -INFINITY) ? 0.f : __expf(c[t][0] - mN0);
            float p1 = (c[t][1] == -INFINITY) ? 0.f : __expf(c[t][1] - mN0);
            float p2 = (c[t][2] == -INFINITY) ? 0.f : __expf(c[t][2] - mN1);
            float p3 = (c[t][3] == -INFINITY) ? 0.f : __expf(c[t][3] - mN1);
            ls0 += p0 + p1; ls1 += p2 + p3;
            if ((t & 1) == 0) { pf[t>>1][0] = h2pack(p0, p1); pf[t>>1][1] = h2pack(p2, p3); }
            else              { pf[t>>1][2] = h2pack(p0, p1); pf[t>>1][3] = h2pack(p2, p3); }
        }
        ls0 += __shfl_xor_sync(0xffffffffu, ls0, 1);
        ls0 += __shfl_xor_sync(0xffffffffu, ls0, 2);
        ls1 += __shfl_xor_sync(0xffffffffu, ls1, 1);
        ls1 += __shfl_xor_sync(0xffffffffu, ls1, 2);
        lrun0 = lrun0 * cor0 + ls0;
        lrun1 = lrun1 * cor1 + ls1;
        mrun0 = mN0; mrun1 = mN1;

        #pragma unroll
        for (int i = 0; i < 16; i++) {
            o[i][0] *= cor0; o[i][1] *= cor0;
            o[i][2] *= cor1; o[i][3] *= cor1;
        }

        // ---- PV: P a-frags direct from registers; V via ldmatrix.trans
        #pragma unroll
        for (int kp = 0; kp < 4; kp++) {
            const int row = kp*16 + vrow;
            const uint32_t rkey = (uint32_t)((row & 7) << 4);
            #pragma unroll
            for (int t = 0; t < 2; t++) {
                const uint32_t vt = sb + 16384 + (uint32_t)t*8192;
                #pragma unroll
                for (int p = 0; p < 4; p++) {
                    const uint32_t bcol = (uint32_t)(p*32 + voct*16) ^ rkey;
                    uint32_t t0, t1, t2, t3;
                    LDSM_X4T(t0, t1, t2, t3, vt + (uint32_t)row*128 + bcol);
                    uint32_t b0[2] = {t0, t1};
                    uint32_t b1[2] = {t2, t3};
                    MMA16816H(o[t*8 + p*2],     pf[kp], b0);
                    MMA16816H(o[t*8 + p*2 + 1], pf[kp], b1);
                }
            }
        }
    }

    // ---- normalize + packed store (raw-reshape [B*S, D] mapping)
    {
        const float inv0 = 1.f / lrun0;
        const float inv1 = 1.f / lrun1;
        const int t0i = (bb*HH + hh)*SS + q0 + rA0;
        const int t1i = (bb*HH + hh)*SS + q0 + rA1;
        const int m0 = t0i >> 4, cB0 = (t0i & 15) * 128;
        const int m1 = t1i >> 4, cB1 = (t1i & 15) * 128;
        #pragma unroll
        for (int ntl = 0; ntl < 16; ntl++) {
            const int cb = ntl*8 + cc;
            pack2H((char*)outP, DD/64, m0, cB0 + cb, o[ntl][0]*inv0, o[ntl][1]*inv0);
            pack2H((char*)outP, DD/64, m1, cB1 + cb, o[ntl][2]*inv1, o[ntl][3]*inv1);
        }
    }
}

// ---------------- launch --------------------------------------------------------
extern "C" void kernel_launch(void* const* d_in, const int* in_sizes, int n_in,
                              void* d_out, int out_size)
{
    (void)in_sizes; (void)n_in; (void)out_size;
    const float* x     = (const float*)d_in[0];
    const float* rms_w = (const float*)d_in[1];
    const float* w_qkv = (const float*)d_in[2];
    const float* w_out = (const float*)d_in[3];
    const float* w1    = (const float*)d_in[4];
    const float* b1    = (const float*)d_in[5];
    const float* w3    = (const float*)d_in[6];
    const float* b3    = (const float*)d_in[7];
    const float* w2    = (const float*)d_in[8];
    const float* b2    = (const float*)d_in[9];
    float* out = (float*)d_out;

    __half *qkvh,*xn2,*att2,*h2,*gg2,*wqkv2,*wout2,*w132,*w22;
    cudaGetSymbolAddress((void**)&qkvh,  g_qkvh);
    cudaGetSymbolAddress((void**)&xn2,   g_xn2);
    cudaGetSymbolAddress((void**)&att2,  g_att2);
    cudaGetSymbolAddress((void**)&h2,    g_h2);
    cudaGetSymbolAddress((void**)&gg2,   g_gg2);
    cudaGetSymbolAddress((void**)&wqkv2, g_wqkv2);
    cudaGetSymbolAddress((void**)&wout2, g_wout2);
    cudaGetSymbolAddress((void**)&w132,  g_w132);
    cudaGetSymbolAddress((void**)&w22,   g_w22);

    cudaFuncSetAttribute(gemm_mma, cudaFuncAttributeMaxDynamicSharedMemorySize, G_SMEM);
    cudaFuncSetAttribute(attn_fp16, cudaFuncAttributeMaxDynamicSharedMemorySize, AT_SMEM);

    // all weight conversions in one launch
    convAll<<<65536, 256>>>(w_qkv, w_out, w1, w3, w2, wqkv2, wout2, w132, w22);

    // 1) RMSNorm -> packed
    rmsnorm_pack<<<MM, 256>>>(x, rms_w, xn2);

    // 2) QKV projection -> fp16 row-major
    gemm_mma<<<dim3(QKVW/128, MM/128), 288, G_SMEM>>>(
        xn2, wqkv2, nullptr, nullptr, nullptr, nullptr, nullptr, qkvh, QKVW, DD/64, 0);

    // 3) attention (128-thr CTAs, register softmax/P) -> packed att2
    attn_fp16<<<dim3(SS/64, HH, BB), 128, AT_SMEM>>>(qkvh, att2);

    // 4) out projection -> packed h2
    gemm_mma<<<dim3(DD/128, MM/128), 288, G_SMEM>>>(
        att2, wout2, nullptr, nullptr, nullptr, nullptr, h2, nullptr, DD, DD/64, 0);

    // 5+6) fused dual-FFN: gg = (h@w1^T + b1) + relu(h@w3^T + b3) -> packed gg2
    gemm_mma<<<dim3(2*FF/128, MM/128), 288, G_SMEM>>>(
        h2, w132, b1, b3, nullptr, nullptr, gg2, nullptr, 2*FF, DD/64, 3);

    // 7) out = x + gg @ w2^T + b2 (fp32 final)
    gemm_mma<<<dim3(DD/128, MM/128), 288, G_SMEM>>>(
        gg2, w22, b2, nullptr, x, out, nullptr, nullptr, DD, FF/64, 2);
}

// round 15
// speedup vs baseline: 1.3351x; 1.0371x over previous
#include <cuda_runtime.h>
#include <cuda_fp16.h>
#include <math.h>
#include <stdint.h>

#define BB   2
#define SS   2048
#define DD   2048
#define HH   16
#define HD   128
#define FF   8192
#define MM   (BB*SS)          // 4096
#define QKVW (3*DD)           // 6144

// ---------------- scratch ----------------
__device__ __half g_qkvh[(size_t)MM*QKVW];     // fp16 row-major qkv
// fp16 packed (tiled [rows/128][K/64][128][64], SW128)
__device__ __half g_xn2 [(size_t)MM*DD];
__device__ __half g_att2[(size_t)MM*DD];
__device__ __half g_h2  [(size_t)MM*DD];
__device__ __half g_gg2 [(size_t)MM*FF];
__device__ __half g_wqkv2[(size_t)QKVW*DD];
__device__ __half g_wout2[(size_t)DD*DD];
__device__ __half g_w132[(size_t)2*FF*DD];     // w1/w3 row-interleaved
__device__ __half g_w22 [(size_t)DD*FF];

// ---------------- PTX helpers -------------------------------------------------
__device__ __forceinline__ uint32_t smem_u32(const void* p) {
    uint32_t a;
    asm("{ .reg .u64 t; cvta.to.shared.u64 t, %1; cvt.u32.u64 %0, t; }" : "=r"(a) : "l"(p));
    return a;
}
__device__ __forceinline__ uint32_t elect_one() {
    uint32_t p;
    asm volatile("{ .reg .pred p; elect.sync _|p, 0xFFFFFFFF; selp.b32 %0,1,0,p; }" : "=r"(p));
    return p;
}
#define MBAR_INIT(a, c) \
    asm volatile("mbarrier.init.shared.b64 [%0], %1;" :: "r"(a), "r"(c) : "memory")
#define MBAR_EXPECT(a, b) \
    asm volatile("mbarrier.arrive.expect_tx.shared.b64 _, [%0], %1;" :: "r"(a), "r"(b) : "memory")
#define MBAR_ARRIVE(a) \
    asm volatile("mbarrier.arrive.shared.b64 _, [%0];" :: "r"(a) : "memory")
#define MBAR_WAIT(a, ph) do { uint32_t _m=(a), _p=(ph), _d;                                   \
    asm volatile("{ .reg .pred p; mbarrier.try_wait.parity.acquire.cta.shared::cta.b64 p, [%1], %2; selp.b32 %0,1,0,p; }" \
                 : "=r"(_d) : "r"(_m), "r"(_p) : "memory");                                   \
    if (!_d) {                                                                                \
      asm volatile("{ .reg .pred P1; WL%=: mbarrier.try_wait.parity.acquire.cta.shared::cta.b64 P1, [%0], %1, 0x989680; @P1 bra.uni WD%=; bra.uni WL%=; WD%=: }" \
                   :: "r"(_m), "r"(_p) : "memory"); } } while(0)
#define BULK_G2S(d, s, n, m) \
    asm volatile("cp.async.bulk.shared::cta.global.mbarrier::complete_tx::bytes [%0], [%1], %2, [%3];" \
                 :: "r"(d), "l"(s), "r"(n), "r"(m) : "memory")
#define CP_ASYNC16(d, s) \
    asm volatile("cp.async.cg.shared.global [%0], [%1], 16;" :: "r"(d), "l"(s) : "memory")
#define CP_COMMIT() asm volatile("cp.async.commit_group;" ::: "memory")
#define CP_WAIT0()  asm volatile("cp.async.wait_group 0;" ::: "memory")
#define LDSM_X4(r0, r1, r2, r3, a) \
    asm volatile("ldmatrix.sync.aligned.m8n8.x4.shared.b16 {%0,%1,%2,%3}, [%4];" \
                 : "=r"(r0), "=r"(r1), "=r"(r2), "=r"(r3) : "r"(a))
#define LDSM_X4T(r0, r1, r2, r3, a) \
    asm volatile("ldmatrix.sync.aligned.m8n8.x4.trans.shared.b16 {%0,%1,%2,%3}, [%4];" \
                 : "=r"(r0), "=r"(r1), "=r"(r2), "=r"(r3) : "r"(a))
#define MMA16816H(d, av, bv) \
    asm volatile("mma.sync.aligned.m16n8k16.row.col.f32.f16.f16.f32 " \
                 "{%0,%1,%2,%3}, {%4,%5,%6,%7}, {%8,%9}, {%0,%1,%2,%3};" \
                 : "+f"((d)[0]), "+f"((d)[1]), "+f"((d)[2]), "+f"((d)[3]) \
                 : "r"((av)[0]), "r"((av)[1]), "r"((av)[2]), "r"((av)[3]), \
                   "r"((bv)[0]), "r"((bv)[1]))

// ---------------- fp16 pack helpers --------------------------------------------
__device__ __forceinline__ uint32_t h2pack(float v0, float v1) {
    return (uint32_t)__half_as_ushort(__float2half_rn(v0))
         | ((uint32_t)__half_as_ushort(__float2half_rn(v1)) << 16);
}
__device__ __forceinline__ void pack4H(char* base, int ktK, int m, int n, float4 v) {
    const int mt = m >> 7, mr = m & 127;
    const int kt = n >> 6, c = n & 63;
    const size_t tb = ((size_t)mt * ktK + kt) * 16384;
    uint32_t off = (uint32_t)(mr * 128 + c * 2);
    off ^= (off >> 3) & 0x70;
    *(uint2*)(base + tb + off) = make_uint2(h2pack(v.x, v.y), h2pack(v.z, v.w));
}
__device__ __forceinline__ void pack2H(char* base, int ktK, int m, int n, float v0, float v1) {
    const int mt = m >> 7, mr = m & 127;
    const int kt = n >> 6, c = n & 63;
    const size_t tb = ((size_t)mt * ktK + kt) * 16384;
    uint32_t off = (uint32_t)(mr * 128 + c * 2);
    off ^= (off >> 3) & 0x70;
    *(uint32_t*)(base + tb + off) = h2pack(v0, v1);
}

// ---------------- RMSNorm -> packed fp16 ---------------------------------------
__global__ __launch_bounds__(256) void rmsnorm_pack(
    const float* __restrict__ x, const float* __restrict__ w, __half* __restrict__ dst)
{
    const int row = blockIdx.x;
    const float4* xr = (const float4*)(x + (size_t)row * DD);
    float4 a = xr[threadIdx.x];
    float4 b = xr[threadIdx.x + 256];
    float ss = a.x*a.x + a.y*a.y + a.z*a.z + a.w*a.w
             + b.x*b.x + b.y*b.y + b.z*b.z + b.w*b.w;
    #pragma unroll
    for (int o = 16; o; o >>= 1) ss += __shfl_xor_sync(0xffffffffu, ss, o);
    __shared__ float sred[8];
    if ((threadIdx.x & 31) == 0) sred[threadIdx.x >> 5] = ss;
    __syncthreads();
    float tot = sred[0]+sred[1]+sred[2]+sred[3]+sred[4]+sred[5]+sred[6]+sred[7];
    float sc = rsqrtf(tot * (1.0f / DD) + 1e-5f);

    const float4* wr = (const float4*)w;
    #pragma unroll
    for (int g = 0; g < 2; g++) {
        const int gi = threadIdx.x + g*256;
        float4 v = (g == 0) ? a : b;
        float4 wv = wr[gi];
        v.x *= sc * wv.x; v.y *= sc * wv.y; v.z *= sc * wv.z; v.w *= sc * wv.w;
        pack4H((char*)dst, DD/64, row, gi*4, v);
    }
}

// ---------------- all weight conversions in ONE launch --------------------------
__global__ __launch_bounds__(256) void convAll(
    const float* __restrict__ wqkv, const float* __restrict__ wout,
    const float* __restrict__ w1,   const float* __restrict__ w3,
    const float* __restrict__ w2,
    __half* __restrict__ dqkv, __half* __restrict__ dout,
    __half* __restrict__ d13,  __half* __restrict__ d2)
{
    int gid = blockIdx.x * 256 + threadIdx.x;
    const float* src; __half* dst; int K, mstep, moff;
    if (gid < 3145728)       { src = wqkv; dst = dqkv; K = DD; mstep = 1; moff = 0; }
    else if (gid < 4194304)  { src = wout; dst = dout; K = DD; mstep = 1; moff = 0; gid -= 3145728; }
    else if (gid < 8388608)  { src = w1;   dst = d13;  K = DD; mstep = 2; moff = 0; gid -= 4194304; }
    else if (gid < 12582912) { src = w3;   dst = d13;  K = DD; mstep = 2; moff = 1; gid -= 8388608; }
    else                     { src = w2;   dst = d2;   K = FF; mstep = 1; moff = 0; gid -= 12582912; }
    const int kq = K >> 2;
    const int m  = gid / kq;
    const int k  = (gid - m * kq) << 2;
    float4 v = *(const float4*)(src + (size_t)m * K + k);
    pack4H((char*)dst, K >> 6, m * mstep + moff, k, v);
}

// ---------------- fp16 mma.sync GEMM (round-12 proven) --------------------------
#define G_STG    3
#define G_TB     16384
#define G_SMEM   (1024 + G_STG*2*G_TB)        // 99328
#define GROUP_M  8

__global__ __launch_bounds__(288, 2) void gemm_mma(
    const __half* __restrict__ A2, const __half* __restrict__ B2,
    const float* __restrict__ bias, const float* __restrict__ bias3,
    const float* __restrict__ E,
    float* __restrict__ C, __half* __restrict__ P, __half* __restrict__ Hrow,
    int N, int ktK, int mode)
{
    extern __shared__ char sm[];
    const uint32_t sb = smem_u32(sm);
    const int tid = threadIdx.x, wid = tid >> 5, lane = tid & 31;

    const uint32_t MFULL  = sb;
    const uint32_t MEMPTY = sb + 256;
    const uint32_t SA     = sb + 1024;
    const uint32_t SBq    = SA + G_STG * G_TB;

    if (tid == 0) {
        #pragma unroll
        for (int s = 0; s < G_STG; s++) { MBAR_INIT(MFULL + s*8, 1); MBAR_INIT(MEMPTY + s*8, 8); }
    }
    __syncthreads();

    const int gridN = gridDim.x;
    const int bid   = blockIdx.y * gridN + blockIdx.x;
    const int tpg   = GROUP_M * gridN;
    const int grp   = bid / tpg, rem = bid - grp * tpg;
    const int mt    = grp * GROUP_M + (rem % GROUP_M);
    const int nt    = rem / GROUP_M;

    float d[2][8][4];
    #pragma unroll
    for (int a = 0; a < 2; a++)
        #pragma unroll
        for (int b = 0; b < 8; b++)
            #pragma unroll
            for (int c = 0; c < 4; c++) d[a][b][c] = 0.f;

    if (wid == 8) {
        if (elect_one()) {
            const char* Ag = (const char*)A2 + (size_t)mt * ktK * G_TB;
            const char* Bg = (const char*)B2 + (size_t)nt * ktK * G_TB;
            int s = 0, ph = 1;
            for (int kt = 0; kt < ktK; kt++) {
                MBAR_WAIT(MEMPTY + s*8, ph);
                MBAR_EXPECT(MFULL + s*8, 2*G_TB);
                BULK_G2S(SA  + s*G_TB, Ag + (size_t)kt*G_TB, G_TB, MFULL + s*8);
                BULK_G2S(SBq + s*G_TB, Bg + (size_t)kt*G_TB, G_TB, MFULL + s*8);
                if (++s == G_STG) { s = 0; ph ^= 1; }
            }
        }
    } else {
        const int wm = (wid & 3) * 32;
        const int wn = (wid >> 2) * 64;
        const uint32_t rsub   = (uint32_t)(((lane >> 3) & 1) * 8 + (lane & 7));
        const uint32_t ksel   = (uint32_t)((lane >> 4) * 16);
        const uint32_t cmask  = (uint32_t)((lane & 7) << 4);
        const uint32_t aRowOff = (uint32_t)(wm + rsub) * 128;
        const uint32_t bRowOff = (uint32_t)(wn + rsub) * 128;

        int s = 0, ph = 0;
        for (int kt = 0; kt < ktK; kt++) {
            MBAR_WAIT(MFULL + s*8, ph);
            const uint32_t sa  = SA  + s*G_TB;
            const uint32_t sbb = SBq + s*G_TB;
            #pragma unroll
            for (int kk4 = 0; kk4 < 4; kk4++) {
                const uint32_t ko = (uint32_t)(kk4*32 + ksel) ^ cmask;
                uint32_t af[2][4];
                #pragma unroll
                for (int mi = 0; mi < 2; mi++)
                    LDSM_X4(af[mi][0], af[mi][1], af[mi][2], af[mi][3],
                            sa + aRowOff + mi*2048 + ko);
                uint32_t bf[8][2];
                #pragma unroll
                for (int ng = 0; ng < 4; ng++) {
                    uint32_t t0, t1, t2, t3;
                    LDSM_X4(t0, t1, t2, t3, sbb + bRowOff + ng*2048 + ko);
                    bf[2*ng][0] = t0; bf[2*ng+1][0] = t1;
                    bf[2*ng][1] = t2; bf[2*ng+1][1] = t3;
                }
                #pragma unroll
                for (int mi = 0; mi < 2; mi++)
                    #pragma unroll
                    for (int ni = 0; ni < 8; ni++)
                        MMA16816H(d[mi][ni], af[mi], bf[ni]);
            }
            if (lane == 0) MBAR_ARRIVE(MEMPTY + s*8);
            if (++s == G_STG) { s = 0; ph ^= 1; }
        }
    }

    __syncthreads();

    float* st = (float*)(sm + 1024);
    if (wid < 8) {
        const int wm = (wid & 3) * 32;
        const int wn = (wid >> 2) * 64;
        const int r0 = lane >> 2;
        const int cc = (lane & 3) * 2;
        #pragma unroll
        for (int mi = 0; mi < 2; mi++)
            #pragma unroll
            for (int ni = 0; ni < 8; ni++) {
                const int r = wm + mi*16 + r0;
                const int c = wn + ni*8 + cc;
                st[r*132 + c]       = d[mi][ni][0];
                st[r*132 + c + 1]   = d[mi][ni][1];
                st[(r+8)*132 + c]   = d[mi][ni][2];
                st[(r+8)*132 + c+1] = d[mi][ni][3];
            }
    }
    __syncthreads();

    if (mode == 3) {
        if (tid < 256) {
            const int r0 = tid >> 4;
            const int cg = (tid & 15) * 4;
            const int nG = nt*64 + cg;
            float4 b1v = *(const float4*)(bias  + nG);
            float4 b3v = *(const float4*)(bias3 + nG);
            #pragma unroll 4
            for (int rp = 0; rp < 8; rp++) {
                const int r = rp*16 + r0;
                float4 u0 = *(float4*)&st[r*132 + cg*2];
                float4 u1 = *(float4*)&st[r*132 + cg*2 + 4];
                float4 g;
                g.x = (u0.x + b1v.x) + fmaxf(u0.y + b3v.x, 0.f);
                g.y = (u0.z + b1v.y) + fmaxf(u0.w + b3v.y, 0.f);
                g.z = (u1.x + b1v.z) + fmaxf(u1.y + b3v.z, 0.f);
                g.w = (u1.z + b1v.w) + fmaxf(u1.w + b3v.w, 0.f);
                pack4H((char*)P, FF/64, mt*128 + r, nG, g);
            }
        }
    } else if (tid < 256) {
        const int r0 = tid >> 5;
        const int c  = (tid & 31) * 4;
        const int n  = nt*128 + c;
        float4 bv = make_float4(0.f, 0.f, 0.f, 0.f);
        if (bias) bv = *(const float4*)(bias + n);
        #pragma unroll 4
        for (int rp = 0; rp < 16; rp++) {
            const int r = rp*8 + r0;
            const size_t idx = (size_t)(mt*128 + r) * N + n;
            float4 v = *(float4*)&st[r*132 + c];
            v.x += bv.x; v.y += bv.y; v.z += bv.z; v.w += bv.w;
            if (mode == 2) {
                float4 e = *(const float4*)(E + idx);
                v.x += e.x; v.y += e.y; v.z += e.z; v.w += e.w;
            }
            if (P)         pack4H((char*)P, N >> 6, mt*128 + r, n, v);
            else if (Hrow) *(uint2*)(Hrow + idx) = make_uint2(h2pack(v.x, v.y), h2pack(v.z, v.w));
            else           *(float4*)(C + idx) = v;
        }
    }
}

// ---------------- fp16 flash attention: cp.async double-buffered K/V -------------
// 4 warps x 16 q-rows (Br=64), full-width warps, softmax/P in registers.
// smem: K0 @0 | K1 @16384 | V0 @32768 | V1 @49152 ; Q staged in K1/V1 at prologue.
#define AT_SMEM 65536
#define ASCALE  0.08838834764831845f

__global__ __launch_bounds__(128, 3) void attn_fp16(
    const __half* __restrict__ qkvh, __half* __restrict__ outP)
{
    extern __shared__ char smc[];
    const uint32_t sb = smem_u32(smc);
    const int tid = threadIdx.x, wid = tid >> 5, lane = tid & 31;
    const int qt = (int)gridDim.x - 1 - (int)blockIdx.x;   // longest CTAs first
    const int hh = blockIdx.y, bb = blockIdx.z;
    const int q0 = qt * 64;

    // ---- prologue: Q (64x128) into K1/V1 regions (regular stores);
    //      K0/V0 (jt=0) via cp.async.
    #pragma unroll
    for (int i = 0; i < 8; i++) {
        const int id = i*128 + tid;              // 0..1023
        const int rr = id >> 4, oc = id & 15;
        uint32_t off = (uint32_t)(rr*128 + (oc & 7)*16);
        off ^= (off >> 3) & 0x70;
        const uint32_t qdst = ((oc >> 3) ? 49152u : 16384u) + off;
        *(uint4*)(smc + qdst) =
            *(const uint4*)(qkvh + (size_t)(bb*SS + q0 + rr) * QKVW + hh*HD + oc*8);
        const uint32_t toff = (uint32_t)(oc >> 3)*8192 + off;
        const __half* base = qkvh + (size_t)(bb*SS + rr) * QKVW + hh*HD + oc*8;
        CP_ASYNC16(sb + toff,          (const void*)(base + 16*HD));   // K0
        CP_ASYNC16(sb + 32768 + toff,  (const void*)(base + 32*HD));   // V0
    }
    CP_COMMIT();
    CP_WAIT0();
    __syncthreads();

    const int wm = wid * 16;
    const uint32_t rsub  = (uint32_t)(((lane >> 3) & 1) * 8 + (lane & 7));
    const uint32_t ksel  = (uint32_t)((lane >> 4) * 16);
    const uint32_t cmask = (uint32_t)((lane & 7) << 4);
    const uint32_t aRowOff = (uint32_t)(wm + rsub) * 128;

    // ---- Q a-fragments into registers (from K1/V1 staging)
    uint32_t qf[8][4];
    #pragma unroll
    for (int ks = 0; ks < 8; ks++) {
        const uint32_t qbase = (ks < 4) ? 16384u : 49152u;
        const uint32_t ko = (uint32_t)((ks & 3)*32 + ksel) ^ cmask;
        LDSM_X4(qf[ks][0], qf[ks][1], qf[ks][2], qf[ks][3], sb + qbase + aRowOff + ko);
    }
    __syncthreads();   // all Q frag reads complete before buf1 is overwritten

    const int rA0 = wm + (lane >> 2), rA1 = rA0 + 8;
    const int cc  = (lane & 3) * 2;
    const int vrow = lane & 15;
    const int voct = lane >> 4;

    float mrun0 = -INFINITY, mrun1 = -INFINITY, lrun0 = 0.f, lrun1 = 0.f;
    float o[16][4];
    #pragma unroll
    for (int i = 0; i < 16; i++)
        #pragma unroll
        for (int j = 0; j < 4; j++) o[i][j] = 0.f;

    const int njt = qt + 1;
    for (int jt = 0; jt < njt; jt++) {
        const int cur = jt & 1;
        const uint32_t kb = sb + (uint32_t)cur*16384;
        const uint32_t vb = sb + 32768 + (uint32_t)cur*16384;

        // ---- issue async prefetch of tile jt+1 into the alternate buffers
        if (jt + 1 < njt) {
            const int j0n = (jt + 1) * 64;
            const uint32_t koff = sb + (uint32_t)(cur ^ 1)*16384;
            const uint32_t voff = sb + 32768 + (uint32_t)(cur ^ 1)*16384;
            #pragma unroll
            for (int i = 0; i < 8; i++) {
                const int id = i*128 + tid;
                const int rr = id >> 4, oc = id & 15;
                uint32_t off = (uint32_t)(rr*128 + (oc & 7)*16);
                off ^= (off >> 3) & 0x70;
                const uint32_t toff = (uint32_t)(oc >> 3)*8192 + off;
                const __half* base = qkvh + (size_t)(bb*SS + j0n + rr) * QKVW + hh*HD + oc*8;
                CP_ASYNC16(koff + toff, (const void*)(base + 16*HD));
                CP_ASYNC16(voff + toff, (const void*)(base + 32*HD));
            }
            CP_COMMIT();
        }

        // ---- QK^T: 16x64 scores per warp, in registers
        float c[8][4];
        #pragma unroll
        for (int i = 0; i < 8; i++)
            #pragma unroll
            for (int j = 0; j < 4; j++) c[i][j] = 0.f;
        #pragma unroll
        for (int ks = 0; ks < 8; ks++) {
            const uint32_t ko = (uint32_t)((ks & 3)*32 + ksel) ^ cmask;
            const uint32_t kt = kb + (uint32_t)(ks >> 2)*8192;
            #pragma unroll
            for (int ng = 0; ng < 4; ng++) {
                uint32_t t0, t1, t2, t3;
                LDSM_X4(t0, t1, t2, t3, kt + (uint32_t)(ng*16 + rsub)*128 + ko);
                uint32_t b0[2] = {t0, t2};
                uint32_t b1[2] = {t1, t3};
                MMA16816H(c[2*ng],   qf[ks], b0);
                MMA16816H(c[2*ng+1], qf[ks], b1);
            }
        }

        // ---- register softmax (rows = 4-lane shfl groups)
        const int lim0 = q0 + rA0 - jt*64;
        const int lim1 = lim0 + 8;
        float mx0 = -INFINITY, mx1 = -INFINITY;
        #pragma unroll
        for (int t = 0; t < 8; t++) {
            const int col = t*8 + cc;
            c[t][0] = (col     > lim0) ? -INFINITY : c[t][0]*ASCALE;
            c[t][1] = (col + 1 > lim0) ? -INFINITY : c[t][1]*ASCALE;
            c[t][2] = (col     > lim1) ? -INFINITY : c[t][2]*ASCALE;
            c[t][3] = (col + 1 > lim1) ? -INFINITY : c[t][3]*ASCALE;
            mx0 = fmaxf(mx0, fmaxf(c[t][0], c[t][1]));
            mx1 = fmaxf(mx1, fmaxf(c[t][2], c[t][3]));
        }
        mx0 = fmaxf(mx0, __shfl_xor_sync(0xffffffffu, mx0, 1));
        mx0 = fmaxf(mx0, __shfl_xor_sync(0xffffffffu, mx0, 2));
        mx1 = fmaxf(mx1, __shfl_xor_sync(0xffffffffu, mx1, 1));
        mx1 = fmaxf(mx1, __shfl_xor_sync(0xffffffffu, mx1, 2));
        const float mN0 = fmaxf(mrun0, mx0), mN1 = fmaxf(mrun1, mx1);
        const float cor0 = __expf(mrun0 - mN0), cor1 = __expf(mrun1 - mN1);
        float ls0 = 0.f, ls1 = 0.f;
        uint32_t pf[4][4];
        #pragma unroll
        for (int t = 0; t < 8; t++) {
            float p0 = (c[t][0] == -INFINITY) ? 0.f : __expf(c[t][0] - mN0);
            float p1 = (c[t][1] == -INFINITY) ? 0.f : __expf(c[t][1] - mN0);
            float p2 = (c[t][2] == -INFINITY) ? 0.f : __expf(c[t][2] - mN1);
            float p3 = (c[t][3] == -INFINITY) ? 0.f : __expf(c[t][3] - mN1);
            ls0 += p0 + p1; ls1 += p2 + p3;
            if ((t & 1) == 0) { pf[t>>1][0] = h2pack(p0, p1); pf[t>>1][1] = h2pack(p2, p3); }
            else              { pf[t>>1][2] = h2pack(p0, p1); pf[t>>1][3] = h2pack(p2, p3); }
        }
        ls0 += __shfl_xor_sync(0xffffffffu, ls0, 1);
        ls0 += __shfl_xor_sync(0xffffffffu, ls0, 2);
        ls1 += __shfl_xor_sync(0xffffffffu, ls1, 1);
        ls1 += __shfl_xor_sync(0xffffffffu, ls1, 2);
        lrun0 = lrun0 * cor0 + ls0;
        lrun1 = lrun1 * cor1 + ls1;
        mrun0 = mN0; mrun1 = mN1;

        #pragma unroll
        for (int i = 0; i < 16; i++) {
            o[i][0] *= cor0; o[i][1] *= cor0;
            o[i][2] *= cor1; o[i][3] *= cor1;
        }

        // ---- PV: P a-frags direct from registers; V via ldmatrix.trans
        #pragma unroll
        for (int kp = 0; kp < 4; kp++) {
            const int row = kp*16 + vrow;
            const uint32_t rkey = (uint32_t)((row & 7) << 4);
            #pragma unroll
            for (int t = 0; t < 2; t++) {
                const uint32_t vt = vb + (uint32_t)t*8192;
                #pragma unroll
                for (int p = 0; p < 4; p++) {
                    const uint32_t bcol = (uint32_t)(p*32 + voct*16) ^ rkey;
                    uint32_t t0, t1, t2, t3;
                    LDSM_X4T(t0, t1, t2, t3, vt + (uint32_t)row*128 + bcol);
                    uint32_t b0[2] = {t0, t1};
                    uint32_t b1[2] = {t2, t3};
                    MMA16816H(o[t*8 + p*2],     pf[kp], b0);
                    MMA16816H(o[t*8 + p*2 + 1], pf[kp], b1);
                }
            }
        }

        CP_WAIT0();
        __syncthreads();   // prefetched tile visible; current buffers free
    }

    // ---- normalize + packed store (raw-reshape [B*S, D] mapping)
    {
        const float inv0 = 1.f / lrun0;
        const float inv1 = 1.f / lrun1;
        const int t0i = (bb*HH + hh)*SS + q0 + rA0;
        const int t1i = (bb*HH + hh)*SS + q0 + rA1;
        const int m0 = t0i >> 4, cB0 = (t0i & 15) * 128;
        const int m1 = t1i >> 4, cB1 = (t1i & 15) * 128;
        #pragma unroll
        for (int ntl = 0; ntl < 16; ntl++) {
            const int cb = ntl*8 + cc;
            pack2H((char*)outP, DD/64, m0, cB0 + cb, o[ntl][0]*inv0, o[ntl][1]*inv0);
            pack2H((char*)outP, DD/64, m1, cB1 + cb, o[ntl][2]*inv1, o[ntl][3]*inv1);
        }
    }
}

// ---------------- launch --------------------------------------------------------
extern "C" void kernel_launch(void* const* d_in, const int* in_sizes, int n_in,
                              void* d_out, int out_size)
{
    (void)in_sizes; (void)n_in; (void)out_size;
    const float* x     = (const float*)d_in[0];
    const float* rms_w = (const float*)d_in[1];
    const float* w_qkv = (const float*)d_in[2];
    const float* w_out = (const float*)d_in[3];
    const float* w1    = (const float*)d_in[4];
    const float* b1    = (const float*)d_in[5];
    const float* w3    = (const float*)d_in[6];
    const float* b3    = (const float*)d_in[7];
    const float* w2    = (const float*)d_in[8];
    const float* b2    = (const float*)d_in[9];
    float* out = (float*)d_out;

    __half *qkvh,*xn2,*att2,*h2,*gg2,*wqkv2,*wout2,*w132,*w22;
    cudaGetSymbolAddress((void**)&qkvh,  g_qkvh);
    cudaGetSymbolAddress((void**)&xn2,   g_xn2);
    cudaGetSymbolAddress((void**)&att2,  g_att2);
    cudaGetSymbolAddress((void**)&h2,    g_h2);
    cudaGetSymbolAddress((void**)&gg2,   g_gg2);
    cudaGetSymbolAddress((void**)&wqkv2, g_wqkv2);
    cudaGetSymbolAddress((void**)&wout2, g_wout2);
    cudaGetSymbolAddress((void**)&w132,  g_w132);
    cudaGetSymbolAddress((void**)&w22,   g_w22);

    cudaFuncSetAttribute(gemm_mma, cudaFuncAttributeMaxDynamicSharedMemorySize, G_SMEM);
    cudaFuncSetAttribute(attn_fp16, cudaFuncAttributeMaxDynamicSharedMemorySize, AT_SMEM);

    // all weight conversions in one launch
    convAll<<<65536, 256>>>(w_qkv, w_out, w1, w3, w2, wqkv2, wout2, w132, w22);

    // 1) RMSNorm -> packed
    rmsnorm_pack<<<MM, 256>>>(x, rms_w, xn2);

    // 2) QKV projection -> fp16 row-major
    gemm_mma<<<dim3(QKVW/128, MM/128), 288, G_SMEM>>>(
        xn2, wqkv2, nullptr, nullptr, nullptr, nullptr, nullptr, qkvh, QKVW, DD/64, 0);

    // 3) attention (cp.async double-buffered) -> packed att2
    attn_fp16<<<dim3(SS/64, HH, BB), 128, AT_SMEM>>>(qkvh, att2);

    // 4) out projection -> packed h2
    gemm_mma<<<dim3(DD/128, MM/128), 288, G_SMEM>>>(
        att2, wout2, nullptr, nullptr, nullptr, nullptr, h2, nullptr, DD, DD/64, 0);

    // 5+6) fused dual-FFN: gg = (h@w1^T + b1) + relu(h@w3^T + b3) -> packed gg2
    gemm_mma<<<dim3(2*FF/128, MM/128), 288, G_SMEM>>>(
        h2, w132, b1, b3, nullptr, nullptr, gg2, nullptr, 2*FF, DD/64, 3);

    // 7) out = x + gg @ w2^T + b2 (fp32 final)
    gemm_mma<<<dim3(DD/128, MM/128), 288, G_SMEM>>>(
        gg2, w22, b2, nullptr, x, out, nullptr, nullptr, DD, FF/64, 2);
}

// round 16
// speedup vs baseline: 1.3582x; 1.0173x over previous
#include <cuda_runtime.h>
#include <cuda_fp16.h>
#include <math.h>
#include <stdint.h>

#define BB   2
#define SS   2048
#define DD   2048
#define HH   16
#define HD   128
#define FF   8192
#define MM   (BB*SS)          // 4096
#define QKVW (3*DD)           // 6144

// ---------------- scratch ----------------
__device__ __half g_qkvh[(size_t)MM*QKVW];     // fp16 row-major qkv
// fp16 packed (tiled [rows/128][K/64][128][64], SW128)
__device__ __half g_xn2 [(size_t)MM*DD];
__device__ __half g_att2[(size_t)MM*DD];
__device__ __half g_h2  [(size_t)MM*DD];
__device__ __half g_gg2 [(size_t)MM*FF];
__device__ __half g_wqkv2[(size_t)QKVW*DD];
__device__ __half g_wout2[(size_t)DD*DD];
__device__ __half g_w132[(size_t)2*FF*DD];     // w1/w3 row-interleaved
__device__ __half g_w22 [(size_t)DD*FF];

// ---------------- PTX helpers -------------------------------------------------
__device__ __forceinline__ uint32_t smem_u32(const void* p) {
    uint32_t a;
    asm("{ .reg .u64 t; cvta.to.shared.u64 t, %1; cvt.u32.u64 %0, t; }" : "=r"(a) : "l"(p));
    return a;
}
__device__ __forceinline__ uint32_t elect_one() {
    uint32_t p;
    asm volatile("{ .reg .pred p; elect.sync _|p, 0xFFFFFFFF; selp.b32 %0,1,0,p; }" : "=r"(p));
    return p;
}
#define MBAR_INIT(a, c) \
    asm volatile("mbarrier.init.shared.b64 [%0], %1;" :: "r"(a), "r"(c) : "memory")
#define MBAR_EXPECT(a, b) \
    asm volatile("mbarrier.arrive.expect_tx.shared.b64 _, [%0], %1;" :: "r"(a), "r"(b) : "memory")
#define MBAR_ARRIVE(a) \
    asm volatile("mbarrier.arrive.shared.b64 _, [%0];" :: "r"(a) : "memory")
#define MBAR_WAIT(a, ph) do { uint32_t _m=(a), _p=(ph), _d;                                   \
    asm volatile("{ .reg .pred p; mbarrier.try_wait.parity.acquire.cta.shared::cta.b64 p, [%1], %2; selp.b32 %0,1,0,p; }" \
                 : "=r"(_d) : "r"(_m), "r"(_p) : "memory");                                   \
    if (!_d) {                                                                                \
      asm volatile("{ .reg .pred P1; WL%=: mbarrier.try_wait.parity.acquire.cta.shared::cta.b64 P1, [%0], %1, 0x989680; @P1 bra.uni WD%=; bra.uni WL%=; WD%=: }" \
                   :: "r"(_m), "r"(_p) : "memory"); } } while(0)
#define BULK_G2S(d, s, n, m) \
    asm volatile("cp.async.bulk.shared::cta.global.mbarrier::complete_tx::bytes [%0], [%1], %2, [%3];" \
                 :: "r"(d), "l"(s), "r"(n), "r"(m) : "memory")
#define CP_ASYNC16(d, s) \
    asm volatile("cp.async.cg.shared.global [%0], [%1], 16;" :: "r"(d), "l"(s) : "memory")
#define CP_COMMIT() asm volatile("cp.async.commit_group;" ::: "memory")
#define CP_WAIT0()  asm volatile("cp.async.wait_group 0;" ::: "memory")
#define LDSM_X4(r0, r1, r2, r3, a) \
    asm volatile("ldmatrix.sync.aligned.m8n8.x4.shared.b16 {%0,%1,%2,%3}, [%4];" \
                 : "=r"(r0), "=r"(r1), "=r"(r2), "=r"(r3) : "r"(a))
#define LDSM_X4T(r0, r1, r2, r3, a) \
    asm volatile("ldmatrix.sync.aligned.m8n8.x4.trans.shared.b16 {%0,%1,%2,%3}, [%4];" \
                 : "=r"(r0), "=r"(r1), "=r"(r2), "=r"(r3) : "r"(a))
#define MMA16816H(d, av, bv) \
    asm volatile("mma.sync.aligned.m16n8k16.row.col.f32.f16.f16.f32 " \
                 "{%0,%1,%2,%3}, {%4,%5,%6,%7}, {%8,%9}, {%0,%1,%2,%3};" \
                 : "+f"((d)[0]), "+f"((d)[1]), "+f"((d)[2]), "+f"((d)[3]) \
                 : "r"((av)[0]), "r"((av)[1]), "r"((av)[2]), "r"((av)[3]), \
                   "r"((bv)[0]), "r"((bv)[1]))

// ---------------- fp16 pack helpers --------------------------------------------
__device__ __forceinline__ uint32_t h2pack(float v0, float v1) {
    return (uint32_t)__half_as_ushort(__float2half_rn(v0))
         | ((uint32_t)__half_as_ushort(__float2half_rn(v1)) << 16);
}
__device__ __forceinline__ void pack4H(char* base, int ktK, int m, int n, float4 v) {
    const int mt = m >> 7, mr = m & 127;
    const int kt = n >> 6, c = n & 63;
    const size_t tb = ((size_t)mt * ktK + kt) * 16384;
    uint32_t off = (uint32_t)(mr * 128 + c * 2);
    off ^= (off >> 3) & 0x70;
    *(uint2*)(base + tb + off) = make_uint2(h2pack(v.x, v.y), h2pack(v.z, v.w));
}
__device__ __forceinline__ void pack2H(char* base, int ktK, int m, int n, float v0, float v1) {
    const int mt = m >> 7, mr = m & 127;
    const int kt = n >> 6, c = n & 63;
    const size_t tb = ((size_t)mt * ktK + kt) * 16384;
    uint32_t off = (uint32_t)(mr * 128 + c * 2);
    off ^= (off >> 3) & 0x70;
    *(uint32_t*)(base + tb + off) = h2pack(v0, v1);
}

// ---------------- rmsnorm + ALL weight conversions in ONE launch -----------------
// blocks [0, MM): rmsnorm row ; blocks [MM, MM+65536): weight conversion
__global__ __launch_bounds__(256) void prep_fused(
    const float* __restrict__ x,    const float* __restrict__ rw,
    const float* __restrict__ wqkv, const float* __restrict__ wout,
    const float* __restrict__ w1,   const float* __restrict__ w3,
    const float* __restrict__ w2,
    __half* __restrict__ dxn,
    __half* __restrict__ dqkv, __half* __restrict__ dout,
    __half* __restrict__ d13,  __half* __restrict__ d2)
{
    if (blockIdx.x < MM) {
        const int row = blockIdx.x;
        const float4* xr = (const float4*)(x + (size_t)row * DD);
        float4 a = xr[threadIdx.x];
        float4 b = xr[threadIdx.x + 256];
        float ss = a.x*a.x + a.y*a.y + a.z*a.z + a.w*a.w
                 + b.x*b.x + b.y*b.y + b.z*b.z + b.w*b.w;
        #pragma unroll
        for (int o = 16; o; o >>= 1) ss += __shfl_xor_sync(0xffffffffu, ss, o);
        __shared__ float sred[8];
        if ((threadIdx.x & 31) == 0) sred[threadIdx.x >> 5] = ss;
        __syncthreads();
        float tot = sred[0]+sred[1]+sred[2]+sred[3]+sred[4]+sred[5]+sred[6]+sred[7];
        float sc = rsqrtf(tot * (1.0f / DD) + 1e-5f);
        const float4* wr = (const float4*)rw;
        #pragma unroll
        for (int g = 0; g < 2; g++) {
            const int gi = threadIdx.x + g*256;
            float4 v = (g == 0) ? a : b;
            float4 wv = wr[gi];
            v.x *= sc * wv.x; v.y *= sc * wv.y; v.z *= sc * wv.z; v.w *= sc * wv.w;
            pack4H((char*)dxn, DD/64, row, gi*4, v);
        }
        return;
    }
    int gid = (blockIdx.x - MM) * 256 + threadIdx.x;
    const float* src; __half* dst; int K, mstep, moff;
    if (gid < 3145728)       { src = wqkv; dst = dqkv; K = DD; mstep = 1; moff = 0; }
    else if (gid < 4194304)  { src = wout; dst = dout; K = DD; mstep = 1; moff = 0; gid -= 3145728; }
    else if (gid < 8388608)  { src = w1;   dst = d13;  K = DD; mstep = 2; moff = 0; gid -= 4194304; }
    else if (gid < 12582912) { src = w3;   dst = d13;  K = DD; mstep = 2; moff = 1; gid -= 8388608; }
    else                     { src = w2;   dst = d2;   K = FF; mstep = 1; moff = 0; gid -= 12582912; }
    const int kq = K >> 2;
    const int m  = gid / kq;
    const int k  = (gid - m * kq) << 2;
    float4 v = *(const float4*)(src + (size_t)m * K + k);
    pack4H((char*)dst, K >> 6, m * mstep + moff, k, v);
}

// ---------------- fp16 mma.sync GEMM (round-12 proven) --------------------------
#define G_STG    3
#define G_TB     16384
#define G_SMEM   (1024 + G_STG*2*G_TB)        // 99328
#define GROUP_M  8

__global__ __launch_bounds__(288, 2) void gemm_mma(
    const __half* __restrict__ A2, const __half* __restrict__ B2,
    const float* __restrict__ bias, const float* __restrict__ bias3,
    const float* __restrict__ E,
    float* __restrict__ C, __half* __restrict__ P, __half* __restrict__ Hrow,
    int N, int ktK, int mode)
{
    extern __shared__ char sm[];
    const uint32_t sb = smem_u32(sm);
    const int tid = threadIdx.x, wid = tid >> 5, lane = tid & 31;

    const uint32_t MFULL  = sb;
    const uint32_t MEMPTY = sb + 256;
    const uint32_t SA     = sb + 1024;
    const uint32_t SBq    = SA + G_STG * G_TB;

    if (tid == 0) {
        #pragma unroll
        for (int s = 0; s < G_STG; s++) { MBAR_INIT(MFULL + s*8, 1); MBAR_INIT(MEMPTY + s*8, 8); }
    }
    __syncthreads();

    const int gridN = gridDim.x;
    const int bid   = blockIdx.y * gridN + blockIdx.x;
    const int tpg   = GROUP_M * gridN;
    const int grp   = bid / tpg, rem = bid - grp * tpg;
    const int mt    = grp * GROUP_M + (rem % GROUP_M);
    const int nt    = rem / GROUP_M;

    float d[2][8][4];
    #pragma unroll
    for (int a = 0; a < 2; a++)
        #pragma unroll
        for (int b = 0; b < 8; b++)
            #pragma unroll
            for (int c = 0; c < 4; c++) d[a][b][c] = 0.f;

    if (wid == 8) {
        if (elect_one()) {
            const char* Ag = (const char*)A2 + (size_t)mt * ktK * G_TB;
            const char* Bg = (const char*)B2 + (size_t)nt * ktK * G_TB;
            int s = 0, ph = 1;
            for (int kt = 0; kt < ktK; kt++) {
                MBAR_WAIT(MEMPTY + s*8, ph);
                MBAR_EXPECT(MFULL + s*8, 2*G_TB);
                BULK_G2S(SA  + s*G_TB, Ag + (size_t)kt*G_TB, G_TB, MFULL + s*8);
                BULK_G2S(SBq + s*G_TB, Bg + (size_t)kt*G_TB, G_TB, MFULL + s*8);
                if (++s == G_STG) { s = 0; ph ^= 1; }
            }
        }
    } else {
        const int wm = (wid & 3) * 32;
        const int wn = (wid >> 2) * 64;
        const uint32_t rsub   = (uint32_t)(((lane >> 3) & 1) * 8 + (lane & 7));
        const uint32_t ksel   = (uint32_t)((lane >> 4) * 16);
        const uint32_t cmask  = (uint32_t)((lane & 7) << 4);
        const uint32_t aRowOff = (uint32_t)(wm + rsub) * 128;
        const uint32_t bRowOff = (uint32_t)(wn + rsub) * 128;

        int s = 0, ph = 0;
        for (int kt = 0; kt < ktK; kt++) {
            MBAR_WAIT(MFULL + s*8, ph);
            const uint32_t sa  = SA  + s*G_TB;
            const uint32_t sbb = SBq + s*G_TB;
            #pragma unroll
            for (int kk4 = 0; kk4 < 4; kk4++) {
                const uint32_t ko = (uint32_t)(kk4*32 + ksel) ^ cmask;
                uint32_t af[2][4];
                #pragma unroll
                for (int mi = 0; mi < 2; mi++)
                    LDSM_X4(af[mi][0], af[mi][1], af[mi][2], af[mi][3],
                            sa + aRowOff + mi*2048 + ko);
                uint32_t bf[8][2];
                #pragma unroll
                for (int ng = 0; ng < 4; ng++) {
                    uint32_t t0, t1, t2, t3;
                    LDSM_X4(t0, t1, t2, t3, sbb + bRowOff + ng*2048 + ko);
                    bf[2*ng][0] = t0; bf[2*ng+1][0] = t1;
                    bf[2*ng][1] = t2; bf[2*ng+1][1] = t3;
                }
                #pragma unroll
                for (int mi = 0; mi < 2; mi++)
                    #pragma unroll
                    for (int ni = 0; ni < 8; ni++)
                        MMA16816H(d[mi][ni], af[mi], bf[ni]);
            }
            if (lane == 0) MBAR_ARRIVE(MEMPTY + s*8);
            if (++s == G_STG) { s = 0; ph ^= 1; }
        }
    }

    __syncthreads();

    float* st = (float*)(sm + 1024);
    if (wid < 8) {
        const int wm = (wid & 3) * 32;
        const int wn = (wid >> 2) * 64;
        const int r0 = lane >> 2;
        const int cc = (lane & 3) * 2;
        #pragma unroll
        for (int mi = 0; mi < 2; mi++)
            #pragma unroll
            for (int ni = 0; ni < 8; ni++) {
                const int r = wm + mi*16 + r0;
                const int c = wn + ni*8 + cc;
                st[r*132 + c]       = d[mi][ni][0];
                st[r*132 + c + 1]   = d[mi][ni][1];
                st[(r+8)*132 + c]   = d[mi][ni][2];
                st[(r+8)*132 + c+1] = d[mi][ni][3];
            }
    }
    __syncthreads();

    if (mode == 3) {
        if (tid < 256) {
            const int r0 = tid >> 4;
            const int cg = (tid & 15) * 4;
            const int nG = nt*64 + cg;
            float4 b1v = *(const float4*)(bias  + nG);
            float4 b3v = *(const float4*)(bias3 + nG);
            #pragma unroll 4
            for (int rp = 0; rp < 8; rp++) {
                const int r = rp*16 + r0;
                float4 u0 = *(float4*)&st[r*132 + cg*2];
                float4 u1 = *(float4*)&st[r*132 + cg*2 + 4];
                float4 g;
                g.x = (u0.x + b1v.x) + fmaxf(u0.y + b3v.x, 0.f);
                g.y = (u0.z + b1v.y) + fmaxf(u0.w + b3v.y, 0.f);
                g.z = (u1.x + b1v.z) + fmaxf(u1.y + b3v.z, 0.f);
                g.w = (u1.z + b1v.w) + fmaxf(u1.w + b3v.w, 0.f);
                pack4H((char*)P, FF/64, mt*128 + r, nG, g);
            }
        }
    } else if (tid < 256) {
        const int r0 = tid >> 5;
        const int c  = (tid & 31) * 4;
        const int n  = nt*128 + c;
        float4 bv = make_float4(0.f, 0.f, 0.f, 0.f);
        if (bias) bv = *(const float4*)(bias + n);
        #pragma unroll 4
        for (int rp = 0; rp < 16; rp++) {
            const int r = rp*8 + r0;
            const size_t idx = (size_t)(mt*128 + r) * N + n;
            float4 v = *(float4*)&st[r*132 + c];
            v.x += bv.x; v.y += bv.y; v.z += bv.z; v.w += bv.w;
            if (mode == 2) {
                float4 e = *(const float4*)(E + idx);
                v.x += e.x; v.y += e.y; v.z += e.z; v.w += e.w;
            }
            if (P)         pack4H((char*)P, N >> 6, mt*128 + r, n, v);
            else if (Hrow) *(uint2*)(Hrow + idx) = make_uint2(h2pack(v.x, v.y), h2pack(v.z, v.w));
            else           *(float4*)(C + idx) = v;
        }
    }
}

// ---------------- fp16 flash attention: cp.async double-buffered K/V -------------
// 4 warps x 16 q-rows (Br=64), full-width warps, softmax/P in registers.
// CEXP = log2(e)/sqrt(128): softmax computed as exp2((s - m) * CEXP) on raw scores.
#define AT_SMEM 65536
#define CEXP    0.12751740f

__global__ __launch_bounds__(128, 3) void attn_fp16(
    const __half* __restrict__ qkvh, __half* __restrict__ outP)
{
    extern __shared__ char smc[];
    const uint32_t sb = smem_u32(smc);
    const int tid = threadIdx.x, wid = tid >> 5, lane = tid & 31;
    const int qt = (int)gridDim.x - 1 - (int)blockIdx.x;   // longest CTAs first
    const int hh = blockIdx.y, bb = blockIdx.z;
    const int q0 = qt * 64;

    // ---- prologue: Q into K1/V1 staging; K0/V0 (jt=0) via cp.async
    #pragma unroll
    for (int i = 0; i < 8; i++) {
        const int id = i*128 + tid;
        const int rr = id >> 4, oc = id & 15;
        uint32_t off = (uint32_t)(rr*128 + (oc & 7)*16);
        off ^= (off >> 3) & 0x70;
        const uint32_t qdst = ((oc >> 3) ? 49152u : 16384u) + off;
        *(uint4*)(smc + qdst) =
            *(const uint4*)(qkvh + (size_t)(bb*SS + q0 + rr) * QKVW + hh*HD + oc*8);
        const uint32_t toff = (uint32_t)(oc >> 3)*8192 + off;
        const __half* base = qkvh + (size_t)(bb*SS + rr) * QKVW + hh*HD + oc*8;
        CP_ASYNC16(sb + toff,          (const void*)(base + 16*HD));
        CP_ASYNC16(sb + 32768 + toff,  (const void*)(base + 32*HD));
    }
    CP_COMMIT();
    CP_WAIT0();
    __syncthreads();

    const int wm = wid * 16;
    const uint32_t rsub  = (uint32_t)(((lane >> 3) & 1) * 8 + (lane & 7));
    const uint32_t ksel  = (uint32_t)((lane >> 4) * 16);
    const uint32_t cmask = (uint32_t)((lane & 7) << 4);
    const uint32_t aRowOff = (uint32_t)(wm + rsub) * 128;

    uint32_t qf[8][4];
    #pragma unroll
    for (int ks = 0; ks < 8; ks++) {
        const uint32_t qbase = (ks < 4) ? 16384u : 49152u;
        const uint32_t ko = (uint32_t)((ks & 3)*32 + ksel) ^ cmask;
        LDSM_X4(qf[ks][0], qf[ks][1], qf[ks][2], qf[ks][3], sb + qbase + aRowOff + ko);
    }
    __syncthreads();

    const int rA0 = wm + (lane >> 2), rA1 = rA0 + 8;
    const int cc  = (lane & 3) * 2;
    const int vrow = lane & 15;
    const int voct = lane >> 4;

    float mrun0 = -INFINITY, mrun1 = -INFINITY, lrun0 = 0.f, lrun1 = 0.f;
    float o[16][4];
    #pragma unroll
    for (int i = 0; i < 16; i++)
        #pragma unroll
        for (int j = 0; j < 4; j++) o[i][j] = 0.f;

    const int njt = qt + 1;
    for (int jt = 0; jt < njt; jt++) {
        const int cur = jt & 1;
        const uint32_t kb = sb + (uint32_t)cur*16384;
        const uint32_t vb = sb + 32768 + (uint32_t)cur*16384;

        if (jt + 1 < njt) {
            const int j0n = (jt + 1) * 64;
            const uint32_t koff = sb + (uint32_t)(cur ^ 1)*16384;
            const uint32_t voff = sb + 32768 + (uint32_t)(cur ^ 1)*16384;
            #pragma unroll
            for (int i = 0; i < 8; i++) {
                const int id = i*128 + tid;
                const int rr = id >> 4, oc = id & 15;
                uint32_t off = (uint32_t)(rr*128 + (oc & 7)*16);
                off ^= (off >> 3) & 0x70;
                const uint32_t toff = (uint32_t)(oc >> 3)*8192 + off;
                const __half* base = qkvh + (size_t)(bb*SS + j0n + rr) * QKVW + hh*HD + oc*8;
                CP_ASYNC16(koff + toff, (const void*)(base + 16*HD));
                CP_ASYNC16(voff + toff, (const void*)(base + 32*HD));
            }
            CP_COMMIT();
        }

        // ---- QK^T (raw scores in registers)
        float c[8][4];
        #pragma unroll
        for (int i = 0; i < 8; i++)
            #pragma unroll
            for (int j = 0; j < 4; j++) c[i][j] = 0.f;
        #pragma unroll
        for (int ks = 0; ks < 8; ks++) {
            const uint32_t ko = (uint32_t)((ks & 3)*32 + ksel) ^ cmask;
            const uint32_t kt = kb + (uint32_t)(ks >> 2)*8192;
            #pragma unroll
            for (int ng = 0; ng < 4; ng++) {
                uint32_t t0, t1, t2, t3;
                LDSM_X4(t0, t1, t2, t3, kt + (uint32_t)(ng*16 + rsub)*128 + ko);
                uint32_t b0[2] = {t0, t2};
                uint32_t b1[2] = {t1, t3};
                MMA16816H(c[2*ng],   qf[ks], b0);
                MMA16816H(c[2*ng+1], qf[ks], b1);
            }
        }

        // ---- register softmax (raw domain; scale folded into exp2)
        float mx0 = -INFINITY, mx1 = -INFINITY;
        float ls0 = 0.f, ls1 = 0.f;
        uint32_t pf[4][4];
        if (jt < qt) {
            // non-diagonal: no masking
            #pragma unroll
            for (int t = 0; t < 8; t++) {
                mx0 = fmaxf(mx0, fmaxf(c[t][0], c[t][1]));
                mx1 = fmaxf(mx1, fmaxf(c[t][2], c[t][3]));
            }
            mx0 = fmaxf(mx0, __shfl_xor_sync(0xffffffffu, mx0, 1));
            mx0 = fmaxf(mx0, __shfl_xor_sync(0xffffffffu, mx0, 2));
            mx1 = fmaxf(mx1, __shfl_xor_sync(0xffffffffu, mx1, 1));
            mx1 = fmaxf(mx1, __shfl_xor_sync(0xffffffffu, mx1, 2));
            const float mN0 = fmaxf(mrun0, mx0), mN1 = fmaxf(mrun1, mx1);
            const float cor0 = exp2f((mrun0 - mN0) * CEXP);
            const float cor1 = exp2f((mrun1 - mN1) * CEXP);
            #pragma unroll
            for (int t = 0; t < 8; t++) {
                float p0 = exp2f((c[t][0] - mN0) * CEXP);
                float p1 = exp2f((c[t][1] - mN0) * CEXP);
                float p2 = exp2f((c[t][2] - mN1) * CEXP);
                float p3 = exp2f((c[t][3] - mN1) * CEXP);
                ls0 += p0 + p1; ls1 += p2 + p3;
                if ((t & 1) == 0) { pf[t>>1][0] = h2pack(p0, p1); pf[t>>1][1] = h2pack(p2, p3); }
                else              { pf[t>>1][2] = h2pack(p0, p1); pf[t>>1][3] = h2pack(p2, p3); }
            }
            ls0 += __shfl_xor_sync(0xffffffffu, ls0, 1);
            ls0 += __shfl_xor_sync(0xffffffffu, ls0, 2);
            ls1 += __shfl_xor_sync(0xffffffffu, ls1, 1);
            ls1 += __shfl_xor_sync(0xffffffffu, ls1, 2);
            lrun0 = lrun0 * cor0 + ls0;
            lrun1 = lrun1 * cor1 + ls1;
            mrun0 = mN0; mrun1 = mN1;
            #pragma unroll
            for (int i = 0; i < 16; i++) {
                o[i][0] *= cor0; o[i][1] *= cor0;
                o[i][2] *= cor1; o[i][3] *= cor1;
            }
        } else {
            // diagonal tile: causal masking
            const int lim0 = rA0;        // q0 == j0 here
            const int lim1 = rA0 + 8;
            #pragma unroll
            for (int t = 0; t < 8; t++) {
                const int col = t*8 + cc;
                c[t][0] = (col     > lim0) ? -INFINITY : c[t][0];
                c[t][1] = (col + 1 > lim0) ? -INFINITY : c[t][1];
                c[t][2] = (col     > lim1) ? -INFINITY : c[t][2];
                c[t][3] = (col + 1 > lim1) ? -INFINITY : c[t][3];
                mx0 = fmaxf(mx0, fmaxf(c[t][0], c[t][1]));
                mx1 = fmaxf(mx1, fmaxf(c[t][2], c[t][3]));
            }
            mx0 = fmaxf(mx0, __shfl_xor_sync(0xffffffffu, mx0, 1));
            mx0 = fmaxf(mx0, __shfl_xor_sync(0xffffffffu, mx0, 2));
            mx1 = fmaxf(mx1, __shfl_xor_sync(0xffffffffu, mx1, 1));
            mx1 = fmaxf(mx1, __shfl_xor_sync(0xffffffffu, mx1, 2));
            const float mN0 = fmaxf(mrun0, mx0), mN1 = fmaxf(mrun1, mx1);
            const float cor0 = exp2f((mrun0 - mN0) * CEXP);
            const float cor1 = exp2f((mrun1 - mN1) * CEXP);
            #pragma unroll
            for (int t = 0; t < 8; t++) {
                float p0 = (c[t][0] == -INFINITY) ? 0.f : exp2f((c[t][0] - mN0) * CEXP);
                float p1 = (c[t][1] == -INFINITY) ? 0.f : exp2f((c[t][1] - mN0) * CEXP);
                float p2 = (c[t][2] == -INFINITY) ? 0.f : exp2f((c[t][2] - mN1) * CEXP);
                float p3 = (c[t][3] == -INFINITY) ? 0.f : exp2f((c[t][3] - mN1) * CEXP);
                ls0 += p0 + p1; ls1 += p2 + p3;
                if ((t & 1) == 0) { pf[t>>1][0] = h2pack(p0, p1); pf[t>>1][1] = h2pack(p2, p3); }
                else              { pf[t>>1][2] = h2pack(p0, p1); pf[t>>1][3] = h2pack(p2, p3); }
            }
            ls0 += __shfl_xor_sync(0xffffffffu, ls0, 1);
            ls0 += __shfl_xor_sync(0xffffffffu, ls0, 2);
            ls1 += __shfl_xor_sync(0xffffffffu, ls1, 1);
            ls1 += __shfl_xor_sync(0xffffffffu, ls1, 2);
            lrun0 = lrun0 * cor0 + ls0;
            lrun1 = lrun1 * cor1 + ls1;
            mrun0 = mN0; mrun1 = mN1;
            #pragma unroll
            for (int i = 0; i < 16; i++) {
                o[i][0] *= cor0; o[i][1] *= cor0;
                o[i][2] *= cor1; o[i][3] *= cor1;
            }
        }

        // ---- PV: P a-frags direct from registers; V via ldmatrix.trans
        #pragma unroll
        for (int kp = 0; kp < 4; kp++) {
            const int row = kp*16 + vrow;
            const uint32_t rkey = (uint32_t)((row & 7) << 4);
            #pragma unroll
            for (int t = 0; t < 2; t++) {
                const uint32_t vt = vb + (uint32_t)t*8192;
                #pragma unroll
                for (int p = 0; p < 4; p++) {
                    const uint32_t bcol = (uint32_t)(p*32 + voct*16) ^ rkey;
                    uint32_t t0, t1, t2, t3;
                    LDSM_X4T(t0, t1, t2, t3, vt + (uint32_t)row*128 + bcol);
                    uint32_t b0[2] = {t0, t1};
                    uint32_t b1[2] = {t2, t3};
                    MMA16816H(o[t*8 + p*2],     pf[kp], b0);
                    MMA16816H(o[t*8 + p*2 + 1], pf[kp], b1);
                }
            }
        }

        CP_WAIT0();
        __syncthreads();
    }

    // ---- normalize + packed store (raw-reshape [B*S, D] mapping)
    {
        const float inv0 = 1.f / lrun0;
        const float inv1 = 1.f / lrun1;
        const int t0i = (bb*HH + hh)*SS + q0 + rA0;
        const int t1i = (bb*HH + hh)*SS + q0 + rA1;
        const int m0 = t0i >> 4, cB0 = (t0i & 15) * 128;
        const int m1 = t1i >> 4, cB1 = (t1i & 15) * 128;
        #pragma unroll
        for (int ntl = 0; ntl < 16; ntl++) {
            const int cb = ntl*8 + cc;
            pack2H((char*)outP, DD/64, m0, cB0 + cb, o[ntl][0]*inv0, o[ntl][1]*inv0);
            pack2H((char*)outP, DD/64, m1, cB1 + cb, o[ntl][2]*inv1, o[ntl][3]*inv1);
        }
    }
}

// ---------------- launch --------------------------------------------------------
extern "C" void kernel_launch(void* const* d_in, const int* in_sizes, int n_in,
                              void* d_out, int out_size)
{
    (void)in_sizes; (void)n_in; (void)out_size;
    const float* x     = (const float*)d_in[0];
    const float* rms_w = (const float*)d_in[1];
    const float* w_qkv = (const float*)d_in[2];
    const float* w_out = (const float*)d_in[3];
    const float* w1    = (const float*)d_in[4];
    const float* b1    = (const float*)d_in[5];
    const float* w3    = (const float*)d_in[6];
    const float* b3    = (const float*)d_in[7];
    const float* w2    = (const float*)d_in[8];
    const float* b2    = (const float*)d_in[9];
    float* out = (float*)d_out;

    __half *qkvh,*xn2,*att2,*h2,*gg2,*wqkv2,*wout2,*w132,*w22;
    cudaGetSymbolAddress((void**)&qkvh,  g_qkvh);
    cudaGetSymbolAddress((void**)&xn2,   g_xn2);
    cudaGetSymbolAddress((void**)&att2,  g_att2);
    cudaGetSymbolAddress((void**)&h2,    g_h2);
    cudaGetSymbolAddress((void**)&gg2,   g_gg2);
    cudaGetSymbolAddress((void**)&wqkv2, g_wqkv2);
    cudaGetSymbolAddress((void**)&wout2, g_wout2);
    cudaGetSymbolAddress((void**)&w132,  g_w132);
    cudaGetSymbolAddress((void**)&w22,   g_w22);

    cudaFuncSetAttribute(gemm_mma, cudaFuncAttributeMaxDynamicSharedMemorySize, G_SMEM);
    cudaFuncSetAttribute(attn_fp16, cudaFuncAttributeMaxDynamicSharedMemorySize, AT_SMEM);

    // rmsnorm + all weight conversions, single launch
    prep_fused<<<MM + 65536, 256>>>(x, rms_w, w_qkv, w_out, w1, w3, w2,
                                    xn2, wqkv2, wout2, w132, w22);

    // 2) QKV projection -> fp16 row-major
    gemm_mma<<<dim3(QKVW/128, MM/128), 288, G_SMEM>>>(
        xn2, wqkv2, nullptr, nullptr, nullptr, nullptr, nullptr, qkvh, QKVW, DD/64, 0);

    // 3) attention (cp.async double-buffered) -> packed att2
    attn_fp16<<<dim3(SS/64, HH, BB), 128, AT_SMEM>>>(qkvh, att2);

    // 4) out projection -> packed h2
    gemm_mma<<<dim3(DD/128, MM/128), 288, G_SMEM>>>(
        att2, wout2, nullptr, nullptr, nullptr, nullptr, h2, nullptr, DD, DD/64, 0);

    // 5+6) fused dual-FFN: gg = (h@w1^T + b1) + relu(h@w3^T + b3) -> packed gg2
    gemm_mma<<<dim3(2*FF/128, MM/128), 288, G_SMEM>>>(
        h2, w132, b1, b3, nullptr, nullptr, gg2, nullptr, 2*FF, DD/64, 3);

    // 7) out = x + gg @ w2^T + b2 (fp32 final)
    gemm_mma<<<dim3(DD/128, MM/128), 288, G_SMEM>>>(
        gg2, w22, b2, nullptr, x, out, nullptr, nullptr, DD, FF/64, 2);
}